// round 3
// baseline (speedup 1.0000x reference)
#include <cuda_runtime.h>
#include <math.h>

// Problem constants
#define BB    8
#define CIN1  512
#define CC    256
#define HH    48
#define WW    48
#define NPIX  2304      // 48*48
#define CR    64        // C/r
#define EPSBN 1e-5f

// ---------------- scratch (static device globals; no cudaMalloc allowed) --------
// Total ~88 MB (was ~260 MB with the full batched attention matrix).
__device__ float g_x1  [(size_t)BB * CC * NPIX];      // after conv1+bn+relu   18.9 MB
__device__ float g_q   [(size_t)BB * CR * NPIX];      //                        4.7 MB
__device__ float g_k   [(size_t)BB * CR * NPIX];      //                        4.7 MB
__device__ float g_v   [(size_t)BB * CC * NPIX];      //                       18.9 MB
__device__ float g_of  [(size_t)BB * CC * NPIX];      // gamma*out + x1        18.9 MB
__device__ float g_attn[(size_t)NPIX * NPIX];         // ONE batch only        21.2 MB

// ---------------- conv3x3 (pad=1) + BN + ReLU, fused -----------------------------
// grid: (C/8 co-tiles, B). block: 256 threads. Each thread: 9 pixels x 8 co.
template<int CIN>
__global__ void conv3x3_bn_relu(const float* __restrict__ x,
                                const float* __restrict__ w,
                                const float* __restrict__ bconv,
                                const float* __restrict__ bg,
                                const float* __restrict__ bb,
                                const float* __restrict__ bm,
                                const float* __restrict__ bv,
                                float* __restrict__ out)
{
    __shared__ float xs[50 * 50];
    __shared__ float ws[8 * 9];

    const int b   = blockIdx.y;
    const int cot = blockIdx.x;          // co = cot*8 + j
    const int tid = threadIdx.x;

    int base[9];
#pragma unroll
    for (int p = 0; p < 9; ++p) {
        int px  = tid + p * 256;
        int row = px / 48;
        int col = px - row * 48;
        base[p] = row * 50 + col;
    }

    float acc[9][8];
#pragma unroll
    for (int p = 0; p < 9; ++p)
#pragma unroll
        for (int j = 0; j < 8; ++j) acc[p][j] = 0.f;

    const int tapoff[9] = {0, 1, 2, 50, 51, 52, 100, 101, 102};

    for (int cin = 0; cin < CIN; ++cin) {
        const float* xp = x + ((size_t)(b * CIN + cin)) * NPIX;
        for (int i = tid; i < 2500; i += 256) {
            int r = i / 50 - 1;
            int c = i - (r + 1) * 50 - 1;
            float v = 0.f;
            if (r >= 0 && r < 48 && c >= 0 && c < 48) v = xp[r * 48 + c];
            xs[i] = v;
        }
        if (tid < 72) {
            int j = tid / 9, tap = tid - j * 9;
            ws[tid] = w[((size_t)(cot * 8 + j) * CIN + cin) * 9 + tap];
        }
        __syncthreads();

#pragma unroll
        for (int tap = 0; tap < 9; ++tap) {
            float wr[8];
#pragma unroll
            for (int j = 0; j < 8; ++j) wr[j] = ws[j * 9 + tap];
            const int to = tapoff[tap];
#pragma unroll
            for (int p = 0; p < 9; ++p) {
                float xv = xs[base[p] + to];
#pragma unroll
                for (int j = 0; j < 8; ++j) acc[p][j] += xv * wr[j];
            }
        }
        __syncthreads();
    }

#pragma unroll
    for (int j = 0; j < 8; ++j) {
        int co = cot * 8 + j;
        float scale = bg[co] * rsqrtf(bv[co] + EPSBN);
        float shift = bb[co] - bm[co] * scale;
        float bc    = bconv[co];
        float* op   = out + ((size_t)(b * CC + co)) * NPIX;
#pragma unroll
        for (int p = 0; p < 9; ++p) {
            float v = (acc[p][j] + bc) * scale + shift;
            op[tid + p * 256] = fmaxf(v, 0.f);
        }
    }
}

// ---------------- generic strided batched SGEMM ----------------------------------
// C[b][m][n] (row-major, ld = N) = sum_k A(b,m,k) * B(b,k,n)  (+bias[m]) (+resid)
__global__ void gemm64(const float* __restrict__ A, long long batchA, int Am, int Ak,
                       const float* __restrict__ B, long long batchB, int Bk, int Bn,
                       float* __restrict__ C, long long batchC,
                       int M, int N, int K,
                       const float* __restrict__ bias,
                       const float* __restrict__ resid, long long batchR,
                       const float* __restrict__ gamma)
{
    __shared__ float As[16][65];
    __shared__ float Bs[16][65];

    const int bz = blockIdx.z;
    const float* Ab = A + (size_t)bz * batchA;
    const float* Bb = B + (size_t)bz * batchB;
    const int m0 = blockIdx.y * 64, n0 = blockIdx.x * 64;
    const int tx = threadIdx.x & 15, ty = threadIdx.x >> 4;

    float acc[4][4];
#pragma unroll
    for (int i = 0; i < 4; ++i)
#pragma unroll
        for (int j = 0; j < 4; ++j) acc[i][j] = 0.f;

    for (int k0 = 0; k0 < K; k0 += 16) {
        if (Ak == 1) {
            for (int i = threadIdx.x; i < 1024; i += 256) {
                int kk = i & 15, mm = i >> 4;
                As[kk][mm] = Ab[(size_t)(m0 + mm) * Am + (k0 + kk)];
            }
        } else {
            for (int i = threadIdx.x; i < 1024; i += 256) {
                int kk = i >> 6, mm = i & 63;
                As[kk][mm] = Ab[(size_t)(m0 + mm) * Am + (size_t)(k0 + kk) * Ak];
            }
        }
        if (Bk == 1) {
            for (int i = threadIdx.x; i < 1024; i += 256) {
                int kk = i & 15, nn = i >> 4;
                Bs[kk][nn] = Bb[(size_t)(k0 + kk) + (size_t)(n0 + nn) * Bn];
            }
        } else {
            for (int i = threadIdx.x; i < 1024; i += 256) {
                int kk = i >> 6, nn = i & 63;
                Bs[kk][nn] = Bb[(size_t)(k0 + kk) * Bk + (size_t)(n0 + nn) * Bn];
            }
        }
        __syncthreads();

#pragma unroll
        for (int kk = 0; kk < 16; ++kk) {
            float a[4], bvv[4];
#pragma unroll
            for (int i = 0; i < 4; ++i) a[i] = As[kk][ty * 4 + i];
#pragma unroll
            for (int j = 0; j < 4; ++j) bvv[j] = Bs[kk][tx * 4 + j];
#pragma unroll
            for (int i = 0; i < 4; ++i)
#pragma unroll
                for (int j = 0; j < 4; ++j) acc[i][j] += a[i] * bvv[j];
        }
        __syncthreads();
    }

    float* Cb = C + (size_t)bz * batchC;
    const float gm = resid ? gamma[0] : 0.f;
#pragma unroll
    for (int i = 0; i < 4; ++i) {
        int m = m0 + ty * 4 + i;
        float bi = bias ? bias[m] : 0.f;
        const float* rp = resid ? (resid + (size_t)bz * batchR + (size_t)m * N) : nullptr;
        float* cp = Cb + (size_t)m * N;
#pragma unroll
        for (int j = 0; j < 4; ++j) {
            int n = n0 + tx * 4 + j;
            float v = acc[i][j] + bi;
            if (rp) v = gm * v + rp[n];
            cp[n] = v;
        }
    }
}

// ---------------- row softmax over 2304 columns ----------------------------------
__global__ void softmax_rows(float* __restrict__ attn)
{
    __shared__ float red[8];
    const size_t row = blockIdx.x;
    float* p = attn + row * (size_t)NPIX;
    const int tid = threadIdx.x;
    const int lane = tid & 31, wid = tid >> 5;

    float v[9];
    float mx = -3.4e38f;
#pragma unroll
    for (int i = 0; i < 9; ++i) {
        v[i] = p[tid + i * 256];
        mx = fmaxf(mx, v[i]);
    }
#pragma unroll
    for (int o = 16; o > 0; o >>= 1) mx = fmaxf(mx, __shfl_xor_sync(0xffffffffu, mx, o));
    if (lane == 0) red[wid] = mx;
    __syncthreads();
    mx = red[0];
#pragma unroll
    for (int i = 1; i < 8; ++i) mx = fmaxf(mx, red[i]);
    __syncthreads();

    float s = 0.f;
#pragma unroll
    for (int i = 0; i < 9; ++i) {
        v[i] = __expf(v[i] - mx);
        s += v[i];
    }
#pragma unroll
    for (int o = 16; o > 0; o >>= 1) s += __shfl_xor_sync(0xffffffffu, s, o);
    if (lane == 0) red[wid] = s;
    __syncthreads();
    s = 0.f;
#pragma unroll
    for (int i = 0; i < 8; ++i) s += red[i];
    const float inv = 1.f / s;
#pragma unroll
    for (int i = 0; i < 9; ++i) p[tid + i * 256] = v[i] * inv;
}

// ---------------- launcher -------------------------------------------------------
extern "C" void kernel_launch(void* const* d_in, const int* in_sizes, int n_in,
                              void* d_out, int out_size)
{
    const float* x     = (const float*)d_in[0];
    const float* w_pre = (const float*)d_in[1];
    const float* b_pre = (const float*)d_in[2];
    const float* bn1g  = (const float*)d_in[3];
    const float* bn1b  = (const float*)d_in[4];
    const float* bn1m  = (const float*)d_in[5];
    const float* bn1v  = (const float*)d_in[6];
    const float* w_q   = (const float*)d_in[7];
    const float* b_q   = (const float*)d_in[8];
    const float* w_k   = (const float*)d_in[9];
    const float* b_k   = (const float*)d_in[10];
    const float* w_v   = (const float*)d_in[11];
    const float* b_v   = (const float*)d_in[12];
    const float* w_f   = (const float*)d_in[13];
    const float* b_f   = (const float*)d_in[14];
    const float* bn2g  = (const float*)d_in[15];
    const float* bn2b  = (const float*)d_in[16];
    const float* bn2m  = (const float*)d_in[17];
    const float* bn2v  = (const float*)d_in[18];
    const float* gamma = (const float*)d_in[19];
    float* out = (float*)d_out;

    float *x1, *q, *k, *v, *of, *attn;
    cudaGetSymbolAddress((void**)&x1,   g_x1);
    cudaGetSymbolAddress((void**)&q,    g_q);
    cudaGetSymbolAddress((void**)&k,    g_k);
    cudaGetSymbolAddress((void**)&v,    g_v);
    cudaGetSymbolAddress((void**)&of,   g_of);
    cudaGetSymbolAddress((void**)&attn, g_attn);

    const long long bX1 = (long long)CC * NPIX;   // 256*2304
    const long long bQK = (long long)CR * NPIX;   // 64*2304

    // 1) conv1 + BN + ReLU  -> x1
    conv3x3_bn_relu<CIN1><<<dim3(CC / 8, BB), 256>>>(x, w_pre, b_pre, bn1g, bn1b, bn1m, bn1v, x1);

    // 2) q = Wq @ x1, k = Wk @ x1, v = Wv @ x1 (1x1 convs), fully batched
    gemm64<<<dim3(NPIX / 64, CR / 64, BB), 256>>>(w_q, 0, CC, 1, x1, bX1, NPIX, 1,
                                                  q, bQK, CR, NPIX, CC, b_q, nullptr, 0, nullptr);
    gemm64<<<dim3(NPIX / 64, CR / 64, BB), 256>>>(w_k, 0, CC, 1, x1, bX1, NPIX, 1,
                                                  k, bQK, CR, NPIX, CC, b_k, nullptr, 0, nullptr);
    gemm64<<<dim3(NPIX / 64, CC / 64, BB), 256>>>(w_v, 0, CC, 1, x1, bX1, NPIX, 1,
                                                  v, bX1, CC, NPIX, CC, b_v, nullptr, 0, nullptr);

    // 3-5) attention, one batch at a time (attn buffer holds a single batch)
    for (int b = 0; b < BB; ++b) {
        const float* qb = q  + (size_t)b * bQK;
        const float* kb = k  + (size_t)b * bQK;
        const float* vb = v  + (size_t)b * bX1;
        const float* xb = x1 + (size_t)b * bX1;
        float*       ob = of + (size_t)b * bX1;

        // energy[i][j] = sum_c q[c][i] * k[c][j]
        gemm64<<<dim3(NPIX / 64, NPIX / 64, 1), 256>>>(qb, 0, 1, NPIX, kb, 0, NPIX, 1,
                                                       attn, 0, NPIX, NPIX, CR,
                                                       nullptr, nullptr, 0, nullptr);
        // row softmax
        softmax_rows<<<NPIX, 256>>>(attn);
        // out[c][i] = sum_j v[c][j] * attn[i][j];  of = gamma*out + x1
        gemm64<<<dim3(NPIX / 64, CC / 64, 1), 256>>>(vb, 0, NPIX, 1, attn, 0, 1, NPIX,
                                                     ob, 0, CC, NPIX, NPIX,
                                                     nullptr, xb, 0, gamma);
    }

    // 6) conv2 + BN + ReLU -> d_out
    conv3x3_bn_relu<CC><<<dim3(CC / 8, BB), 256>>>(of, w_f, b_f, bn2g, bn2b, bn2m, bn2v, out);
}

// round 4
// speedup vs baseline: 1.3385x; 1.3385x over previous
#include <cuda_runtime.h>
#include <math.h>

// Problem constants
#define BB    8
#define CIN1  512
#define CC    256
#define HH    48
#define WW    48
#define NPIX  2304      // 48*48
#define CR    64        // C/r
#define EPSBN 1e-5f
#define CHUNK 4         // attention batches processed per chunk

// ---------------- scratch (static device globals; no cudaMalloc allowed) --------
// Total ~151 MB (R3's 88 MB passed; the 260 MB version coincided with container
// failures, so keep well below that).
__device__ float g_x1  [(size_t)BB * CC * NPIX];        // 18.9 MB
__device__ float g_q   [(size_t)BB * CR * NPIX];        //  4.7 MB
__device__ float g_k   [(size_t)BB * CR * NPIX];        //  4.7 MB
__device__ float g_v   [(size_t)BB * CC * NPIX];        // 18.9 MB
__device__ float g_of  [(size_t)BB * CC * NPIX];        // 18.9 MB
__device__ float g_attn[(size_t)CHUNK * NPIX * NPIX];   // 84.9 MB

// ---------------- conv3x3 (pad=1) + BN + ReLU, fused -----------------------------
template<int CIN>
__global__ void conv3x3_bn_relu(const float* __restrict__ x,
                                const float* __restrict__ w,
                                const float* __restrict__ bconv,
                                const float* __restrict__ bg,
                                const float* __restrict__ bb,
                                const float* __restrict__ bm,
                                const float* __restrict__ bv,
                                float* __restrict__ out)
{
    __shared__ float xs[50 * 50];
    __shared__ float ws[8 * 9];

    const int b   = blockIdx.y;
    const int cot = blockIdx.x;
    const int tid = threadIdx.x;

    int base[9];
#pragma unroll
    for (int p = 0; p < 9; ++p) {
        int px  = tid + p * 256;
        int row = px / 48;
        int col = px - row * 48;
        base[p] = row * 50 + col;
    }

    float acc[9][8];
#pragma unroll
    for (int p = 0; p < 9; ++p)
#pragma unroll
        for (int j = 0; j < 8; ++j) acc[p][j] = 0.f;

    const int tapoff[9] = {0, 1, 2, 50, 51, 52, 100, 101, 102};

    for (int cin = 0; cin < CIN; ++cin) {
        const float* xp = x + ((size_t)(b * CIN + cin)) * NPIX;
        for (int i = tid; i < 2500; i += 256) {
            int r = i / 50 - 1;
            int c = i - (r + 1) * 50 - 1;
            float v = 0.f;
            if (r >= 0 && r < 48 && c >= 0 && c < 48) v = xp[r * 48 + c];
            xs[i] = v;
        }
        if (tid < 72) {
            int j = tid / 9, tap = tid - j * 9;
            ws[tid] = w[((size_t)(cot * 8 + j) * CIN + cin) * 9 + tap];
        }
        __syncthreads();

#pragma unroll
        for (int tap = 0; tap < 9; ++tap) {
            float wr[8];
#pragma unroll
            for (int j = 0; j < 8; ++j) wr[j] = ws[j * 9 + tap];
            const int to = tapoff[tap];
#pragma unroll
            for (int p = 0; p < 9; ++p) {
                float xv = xs[base[p] + to];
#pragma unroll
                for (int j = 0; j < 8; ++j) acc[p][j] += xv * wr[j];
            }
        }
        __syncthreads();
    }

#pragma unroll
    for (int j = 0; j < 8; ++j) {
        int co = cot * 8 + j;
        float scale = bg[co] * rsqrtf(bv[co] + EPSBN);
        float shift = bb[co] - bm[co] * scale;
        float bc    = bconv[co];
        float* op   = out + ((size_t)(b * CC + co)) * NPIX;
#pragma unroll
        for (int p = 0; p < 9; ++p) {
            float v = (acc[p][j] + bc) * scale + shift;
            op[tid + p * 256] = fmaxf(v, 0.f);
        }
    }
}

// ---------------- templated tiled SGEMM -------------------------------------------
// C[b][m][n] (row-major, ld = N) = sum_k A(b,m,k) * B(b,k,n)  (+bias[m]) (+resid)
// A(b,m,k) = A[b*batchA + m*Am + k*Ak];  B(b,k,n) = B[b*batchB + k*Bk + n*Bn]
// If resid != null: C = gamma[0]*C + resid[b*batchR + m*N + n]
// Tile TM x TN x 16, 256 threads, (TM/16)x(TN/16) per thread.
template<int TM, int TN>
__global__ void __launch_bounds__(256) gemmT(
        const float* __restrict__ A, long long batchA, int Am, int Ak,
        const float* __restrict__ B, long long batchB, int Bk, int Bn,
        float* __restrict__ C, long long batchC,
        int M, int N, int K,
        const float* __restrict__ bias,
        const float* __restrict__ resid, long long batchR,
        const float* __restrict__ gamma)
{
    constexpr int RM = TM / 16;
    constexpr int RN = TN / 16;
    __shared__ float As[16][TM];
    __shared__ float Bs[16][TN];

    const int bz = blockIdx.z;
    const float* Ab = A + (size_t)bz * batchA;
    const float* Bb = B + (size_t)bz * batchB;
    const int m0 = blockIdx.y * TM, n0 = blockIdx.x * TN;
    const int tid = threadIdx.x;
    const int tx = tid & 15, ty = tid >> 4;

    float acc[RM][RN];
#pragma unroll
    for (int i = 0; i < RM; ++i)
#pragma unroll
        for (int j = 0; j < RN; ++j) acc[i][j] = 0.f;

    for (int k0 = 0; k0 < K; k0 += 16) {
        // --- stage A tile: As[kk][mm] = A(m0+mm, k0+kk)
        if (Ak == 1) {          // contiguous along k
#pragma unroll
            for (int i = tid; i < TM * 16; i += 256) {
                int kk = i & 15, mm = i >> 4;
                As[kk][mm] = Ab[(size_t)(m0 + mm) * Am + (k0 + kk)];
            }
        } else {                // contiguous along m (Am small/1)
#pragma unroll
            for (int i = tid; i < TM * 16; i += 256) {
                int mm = i % TM, kk = i / TM;
                As[kk][mm] = Ab[(size_t)(m0 + mm) * Am + (size_t)(k0 + kk) * Ak];
            }
        }
        // --- stage B tile: Bs[kk][nn] = B(k0+kk, n0+nn)
        if (Bk == 1) {          // contiguous along k
#pragma unroll
            for (int i = tid; i < TN * 16; i += 256) {
                int kk = i & 15, nn = i >> 4;
                Bs[kk][nn] = Bb[(size_t)(k0 + kk) + (size_t)(n0 + nn) * Bn];
            }
        } else {                // contiguous along n (Bn small/1)
#pragma unroll
            for (int i = tid; i < TN * 16; i += 256) {
                int nn = i % TN, kk = i / TN;
                Bs[kk][nn] = Bb[(size_t)(k0 + kk) * Bk + (size_t)(n0 + nn) * Bn];
            }
        }
        __syncthreads();

#pragma unroll
        for (int kk = 0; kk < 16; ++kk) {
            float a[RM], bv[RN];
#pragma unroll
            for (int i = 0; i < RM; ++i) a[i] = As[kk][ty * RM + i];
#pragma unroll
            for (int j = 0; j < RN; ++j) bv[j] = Bs[kk][tx * RN + j];
#pragma unroll
            for (int i = 0; i < RM; ++i)
#pragma unroll
                for (int j = 0; j < RN; ++j) acc[i][j] += a[i] * bv[j];
        }
        __syncthreads();
    }

    float* Cb = C + (size_t)bz * batchC;
    const float gm = resid ? gamma[0] : 0.f;
#pragma unroll
    for (int i = 0; i < RM; ++i) {
        int m = m0 + ty * RM + i;
        float bi = bias ? bias[m] : 0.f;
        const float* rp = resid ? (resid + (size_t)bz * batchR + (size_t)m * N) : nullptr;
        float* cp = Cb + (size_t)m * N;
#pragma unroll
        for (int j = 0; j < RN; ++j) {
            int n = n0 + tx * RN + j;
            float v = acc[i][j] + bi;
            if (rp) v = gm * v + rp[n];
            cp[n] = v;
        }
    }
}

// ---------------- row softmax over 2304 columns ----------------------------------
__global__ void softmax_rows(float* __restrict__ attn)
{
    __shared__ float red[8];
    const size_t row = blockIdx.x;
    float* p = attn + row * (size_t)NPIX;
    const int tid = threadIdx.x;
    const int lane = tid & 31, wid = tid >> 5;

    float v[9];
    float mx = -3.4e38f;
#pragma unroll
    for (int i = 0; i < 9; ++i) {
        v[i] = p[tid + i * 256];
        mx = fmaxf(mx, v[i]);
    }
#pragma unroll
    for (int o = 16; o > 0; o >>= 1) mx = fmaxf(mx, __shfl_xor_sync(0xffffffffu, mx, o));
    if (lane == 0) red[wid] = mx;
    __syncthreads();
    mx = red[0];
#pragma unroll
    for (int i = 1; i < 8; ++i) mx = fmaxf(mx, red[i]);
    __syncthreads();

    float s = 0.f;
#pragma unroll
    for (int i = 0; i < 9; ++i) {
        v[i] = __expf(v[i] - mx);
        s += v[i];
    }
#pragma unroll
    for (int o = 16; o > 0; o >>= 1) s += __shfl_xor_sync(0xffffffffu, s, o);
    if (lane == 0) red[wid] = s;
    __syncthreads();
    s = 0.f;
#pragma unroll
    for (int i = 0; i < 8; ++i) s += red[i];
    const float inv = 1.f / s;
#pragma unroll
    for (int i = 0; i < 9; ++i) p[tid + i * 256] = v[i] * inv;
}

// ---------------- launcher -------------------------------------------------------
extern "C" void kernel_launch(void* const* d_in, const int* in_sizes, int n_in,
                              void* d_out, int out_size)
{
    const float* x     = (const float*)d_in[0];
    const float* w_pre = (const float*)d_in[1];
    const float* b_pre = (const float*)d_in[2];
    const float* bn1g  = (const float*)d_in[3];
    const float* bn1b  = (const float*)d_in[4];
    const float* bn1m  = (const float*)d_in[5];
    const float* bn1v  = (const float*)d_in[6];
    const float* w_q   = (const float*)d_in[7];
    const float* b_q   = (const float*)d_in[8];
    const float* w_k   = (const float*)d_in[9];
    const float* b_k   = (const float*)d_in[10];
    const float* w_v   = (const float*)d_in[11];
    const float* b_v   = (const float*)d_in[12];
    const float* w_f   = (const float*)d_in[13];
    const float* b_f   = (const float*)d_in[14];
    const float* bn2g  = (const float*)d_in[15];
    const float* bn2b  = (const float*)d_in[16];
    const float* bn2m  = (const float*)d_in[17];
    const float* bn2v  = (const float*)d_in[18];
    const float* gamma = (const float*)d_in[19];
    float* out = (float*)d_out;

    float *x1, *q, *k, *v, *of, *attn;
    cudaGetSymbolAddress((void**)&x1,   g_x1);
    cudaGetSymbolAddress((void**)&q,    g_q);
    cudaGetSymbolAddress((void**)&k,    g_k);
    cudaGetSymbolAddress((void**)&v,    g_v);
    cudaGetSymbolAddress((void**)&of,   g_of);
    cudaGetSymbolAddress((void**)&attn, g_attn);

    const long long bX1 = (long long)CC * NPIX;   // 256*2304
    const long long bQK = (long long)CR * NPIX;   // 64*2304
    const long long bAT = (long long)NPIX * NPIX; // 2304*2304

    // 1) conv1 + BN + ReLU  -> x1
    conv3x3_bn_relu<CIN1><<<dim3(CC / 8, BB), 256>>>(x, w_pre, b_pre, bn1g, bn1b, bn1m, bn1v, x1);

    // 2) q/k/v projections (1x1 convs), fully batched over z
    gemmT<64, 128><<<dim3(NPIX / 128, CR / 64, BB), 256>>>(
        w_q, 0, CC, 1, x1, bX1, NPIX, 1, q, bQK, CR, NPIX, CC, b_q, nullptr, 0, nullptr);
    gemmT<64, 128><<<dim3(NPIX / 128, CR / 64, BB), 256>>>(
        w_k, 0, CC, 1, x1, bX1, NPIX, 1, k, bQK, CR, NPIX, CC, b_k, nullptr, 0, nullptr);
    gemmT<128, 128><<<dim3(NPIX / 128, CC / 128, BB), 256>>>(
        w_v, 0, CC, 1, x1, bX1, NPIX, 1, v, bX1, CC, NPIX, CC, b_v, nullptr, 0, nullptr);

    // 3-5) attention in chunks of CHUNK batches
    for (int c0 = 0; c0 < BB; c0 += CHUNK) {
        const float* qb = q  + (size_t)c0 * bQK;
        const float* kb = k  + (size_t)c0 * bQK;
        const float* vb = v  + (size_t)c0 * bX1;
        const float* xb = x1 + (size_t)c0 * bX1;
        float*       ob = of + (size_t)c0 * bX1;

        // energy[i][j] = sum_c q[c][i] * k[c][j]   (A contiguous in m, B in n)
        gemmT<128, 128><<<dim3(NPIX / 128, NPIX / 128, CHUNK), 256>>>(
            qb, bQK, 1, NPIX, kb, bQK, NPIX, 1,
            attn, bAT, NPIX, NPIX, CR, nullptr, nullptr, 0, nullptr);

        // row softmax
        softmax_rows<<<CHUNK * NPIX, 256>>>(attn);

        // out[c][i] = sum_j v[c][j] * attn[i][j];  of = gamma*out + x1
        gemmT<128, 128><<<dim3(NPIX / 128, CC / 128, CHUNK), 256>>>(
            vb, bX1, NPIX, 1, attn, bAT, 1, NPIX,
            ob, bX1, CC, NPIX, NPIX, nullptr, xb, bX1, gamma);
    }

    // 6) conv2 + BN + ReLU -> d_out
    conv3x3_bn_relu<CC><<<dim3(CC / 8, BB), 256>>>(of, w_f, b_f, bn2g, bn2b, bn2m, bn2v, out);
}

// round 7
// speedup vs baseline: 1.4426x; 1.0778x over previous
#include <cuda_runtime.h>
#include <math.h>
#include <stdint.h>

// Problem constants
#define BB    8
#define CIN1  512
#define CC    256
#define HH    48
#define WW    48
#define NPIX  2304      // 48*48
#define CR    64        // C/r
#define EPSBN 1e-5f
#define CHUNK 4         // attention batches processed per chunk

// ---------------- scratch (static device globals; ~151 MB total) ----------------
__device__ float g_x1  [(size_t)BB * CC * NPIX];
__device__ float g_q   [(size_t)BB * CR * NPIX];
__device__ float g_k   [(size_t)BB * CR * NPIX];
__device__ float g_v   [(size_t)BB * CC * NPIX];
__device__ float g_of  [(size_t)BB * CC * NPIX];
__device__ float g_attn[(size_t)CHUNK * NPIX * NPIX];

// ---------------- conv3x3 (pad=1) + BN + ReLU, fused -----------------------------
template<int CIN>
__global__ void conv3x3_bn_relu(const float* __restrict__ x,
                                const float* __restrict__ w,
                                const float* __restrict__ bconv,
                                const float* __restrict__ bg,
                                const float* __restrict__ bb,
                                const float* __restrict__ bm,
                                const float* __restrict__ bv,
                                float* __restrict__ out)
{
    __shared__ float xs[50 * 50];
    __shared__ float ws[8 * 9];

    const int b   = blockIdx.y;
    const int cot = blockIdx.x;
    const int tid = threadIdx.x;

    int base[9];
#pragma unroll
    for (int p = 0; p < 9; ++p) {
        int px  = tid + p * 256;
        int row = px / 48;
        int col = px - row * 48;
        base[p] = row * 50 + col;
    }

    float acc[9][8];
#pragma unroll
    for (int p = 0; p < 9; ++p)
#pragma unroll
        for (int j = 0; j < 8; ++j) acc[p][j] = 0.f;

    const int tapoff[9] = {0, 1, 2, 50, 51, 52, 100, 101, 102};

    for (int cin = 0; cin < CIN; ++cin) {
        const float* xp = x + ((size_t)(b * CIN + cin)) * NPIX;
        for (int i = tid; i < 2500; i += 256) {
            int r = i / 50 - 1;
            int c = i - (r + 1) * 50 - 1;
            float v = 0.f;
            if (r >= 0 && r < 48 && c >= 0 && c < 48) v = xp[r * 48 + c];
            xs[i] = v;
        }
        if (tid < 72) {
            int j = tid / 9, tap = tid - j * 9;
            ws[tid] = w[((size_t)(cot * 8 + j) * CIN + cin) * 9 + tap];
        }
        __syncthreads();

#pragma unroll
        for (int tap = 0; tap < 9; ++tap) {
            float wr[8];
#pragma unroll
            for (int j = 0; j < 8; ++j) wr[j] = ws[j * 9 + tap];
            const int to = tapoff[tap];
#pragma unroll
            for (int p = 0; p < 9; ++p) {
                float xv = xs[base[p] + to];
#pragma unroll
                for (int j = 0; j < 8; ++j) acc[p][j] += xv * wr[j];
            }
        }
        __syncthreads();
    }

#pragma unroll
    for (int j = 0; j < 8; ++j) {
        int co = cot * 8 + j;
        float scale = bg[co] * rsqrtf(bv[co] + EPSBN);
        float shift = bb[co] - bm[co] * scale;
        float bc    = bconv[co];
        float* op   = out + ((size_t)(b * CC + co)) * NPIX;
#pragma unroll
        for (int p = 0; p < 9; ++p) {
            float v = (acc[p][j] + bc) * scale + shift;
            op[tid + p * 256] = fmaxf(v, 0.f);
        }
    }
}

// ---------------- fp32 tiled SGEMM (precision-critical path: q/k/energy) ---------
template<int TM, int TN>
__global__ void __launch_bounds__(256) gemmT(
        const float* __restrict__ A, long long batchA, int Am, int Ak,
        const float* __restrict__ B, long long batchB, int Bk, int Bn,
        float* __restrict__ C, long long batchC,
        int M, int N, int K,
        const float* __restrict__ bias,
        const float* __restrict__ resid, long long batchR,
        const float* __restrict__ gamma)
{
    constexpr int RM = TM / 16;
    constexpr int RN = TN / 16;
    __shared__ float As[16][TM];
    __shared__ float Bs[16][TN];

    const int bz = blockIdx.z;
    const float* Ab = A + (size_t)bz * batchA;
    const float* Bb = B + (size_t)bz * batchB;
    const int m0 = blockIdx.y * TM, n0 = blockIdx.x * TN;
    const int tid = threadIdx.x;
    const int tx = tid & 15, ty = tid >> 4;

    float acc[RM][RN];
#pragma unroll
    for (int i = 0; i < RM; ++i)
#pragma unroll
        for (int j = 0; j < RN; ++j) acc[i][j] = 0.f;

    for (int k0 = 0; k0 < K; k0 += 16) {
        if (Ak == 1) {
#pragma unroll
            for (int i = tid; i < TM * 16; i += 256) {
                int kk = i & 15, mm = i >> 4;
                As[kk][mm] = Ab[(size_t)(m0 + mm) * Am + (k0 + kk)];
            }
        } else {
#pragma unroll
            for (int i = tid; i < TM * 16; i += 256) {
                int mm = i % TM, kk = i / TM;
                As[kk][mm] = Ab[(size_t)(m0 + mm) * Am + (size_t)(k0 + kk) * Ak];
            }
        }
        if (Bk == 1) {
#pragma unroll
            for (int i = tid; i < TN * 16; i += 256) {
                int kk = i & 15, nn = i >> 4;
                Bs[kk][nn] = Bb[(size_t)(k0 + kk) + (size_t)(n0 + nn) * Bn];
            }
        } else {
#pragma unroll
            for (int i = tid; i < TN * 16; i += 256) {
                int nn = i % TN, kk = i / TN;
                Bs[kk][nn] = Bb[(size_t)(k0 + kk) * Bk + (size_t)(n0 + nn) * Bn];
            }
        }
        __syncthreads();

#pragma unroll
        for (int kk = 0; kk < 16; ++kk) {
            float a[RM], bv[RN];
#pragma unroll
            for (int i = 0; i < RM; ++i) a[i] = As[kk][ty * RM + i];
#pragma unroll
            for (int j = 0; j < RN; ++j) bv[j] = Bs[kk][tx * RN + j];
#pragma unroll
            for (int i = 0; i < RM; ++i)
#pragma unroll
                for (int j = 0; j < RN; ++j) acc[i][j] += a[i] * bv[j];
        }
        __syncthreads();
    }

    float* Cb = C + (size_t)bz * batchC;
    const float gm = resid ? gamma[0] : 0.f;
#pragma unroll
    for (int i = 0; i < RM; ++i) {
        int m = m0 + ty * RM + i;
        float bi = bias ? bias[m] : 0.f;
        const float* rp = resid ? (resid + (size_t)bz * batchR + (size_t)m * N) : nullptr;
        float* cp = Cb + (size_t)m * N;
#pragma unroll
        for (int j = 0; j < RN; ++j) {
            int n = n0 + tx * RN + j;
            float v = acc[i][j] + bi;
            if (rp) v = gm * v + rp[n];
            cp[n] = v;
        }
    }
}

// ---------------- tf32 tensor-core GEMM (tolerant path: v-proj, attn*V) ----------
// C[b][m][n] = sum_k A(b,m,k)*B(b,k,n) (+bias[m]) (+resid: C = gamma*C + resid)
// A must be k-contiguous: A(b,m,k) = A[b*batchA + m*Am + k]
// B: if Bk==1 (k-contiguous): B[b*batchB + k + n*Bn]
//    else (n-contiguous, Bn==1): B[b*batchB + k*Bk + n]
// Tile 128x128, K-chunk 32, 256 threads = 8 warps (2M x 4N), warp tile 64x32.
__device__ __forceinline__ uint32_t f2tf32(float f) {
    uint32_t r;
    asm("cvt.rna.tf32.f32 %0, %1;" : "=r"(r) : "f"(f));
    return r;
}
__device__ __forceinline__ void mma_tf32(float* d, const uint32_t* a, const uint32_t* b) {
    asm volatile(
        "mma.sync.aligned.m16n8k8.row.col.f32.tf32.tf32.f32 "
        "{%0,%1,%2,%3}, {%4,%5,%6,%7}, {%8,%9}, {%0,%1,%2,%3};"
        : "+f"(d[0]), "+f"(d[1]), "+f"(d[2]), "+f"(d[3])
        : "r"(a[0]), "r"(a[1]), "r"(a[2]), "r"(a[3]), "r"(b[0]), "r"(b[1]));
}

__global__ void __launch_bounds__(256) gemm_tf32(
        const float* __restrict__ A, long long batchA, int Am,
        const float* __restrict__ B, long long batchB, int Bk, int Bn,
        float* __restrict__ C, long long batchC,
        int M, int N, int K,
        const float* __restrict__ bias,
        const float* __restrict__ resid, long long batchR,
        const float* __restrict__ gamma)
{
    // swizzled layout: X[row*32 + (kk ^ ((row&7)<<2))]
    __shared__ uint32_t As[128 * 32];
    __shared__ uint32_t Bs[128 * 32];

    const int bz  = blockIdx.z;
    const float* Ab = A + (size_t)bz * batchA;
    const float* Bb = B + (size_t)bz * batchB;
    const int m0 = blockIdx.y * 128, n0 = blockIdx.x * 128;
    const int tid  = threadIdx.x;
    const int wid  = tid >> 5, lane = tid & 31;
    const int g    = lane >> 2, tig = lane & 3;
    const int wm0  = (wid & 1) * 64;        // warp M offset in tile
    const int wn0  = (wid >> 1) * 32;       // warp N offset in tile

    float acc[4][4][4];
#pragma unroll
    for (int i = 0; i < 4; ++i)
#pragma unroll
        for (int j = 0; j < 4; ++j)
#pragma unroll
            for (int c = 0; c < 4; ++c) acc[i][j][c] = 0.f;

    for (int k0 = 0; k0 < K; k0 += 32) {
        // stage A (k-contiguous): coalesced, conflict-free STS
#pragma unroll
        for (int i = tid; i < 4096; i += 256) {
            int kk = i & 31, mm = i >> 5;
            As[mm * 32 + (kk ^ ((mm & 7) << 2))] =
                f2tf32(Ab[(size_t)(m0 + mm) * Am + (k0 + kk)]);
        }
        if (Bk == 1) {
            // B k-contiguous (attn case): coalesced, conflict-free STS
#pragma unroll
            for (int i = tid; i < 4096; i += 256) {
                int kk = i & 31, nn = i >> 5;
                Bs[nn * 32 + (kk ^ ((nn & 7) << 2))] =
                    f2tf32(Bb[(size_t)(k0 + kk) + (size_t)(n0 + nn) * Bn]);
            }
        } else {
            // B n-contiguous (x1 case, Bn==1): coalesced LDG
#pragma unroll
            for (int i = tid; i < 4096; i += 256) {
                int nn = i & 127, kk = i >> 7;
                Bs[nn * 32 + (kk ^ ((nn & 7) << 2))] =
                    f2tf32(Bb[(size_t)(k0 + kk) * Bk + (n0 + nn)]);
            }
        }
        __syncthreads();

#pragma unroll
        for (int ks = 0; ks < 4; ++ks) {
            const int kk = ks * 8 + tig;
            uint32_t af[4][4], bf[4][2];
#pragma unroll
            for (int ms = 0; ms < 4; ++ms) {
                int mm = wm0 + ms * 16 + g;
                int sw = (g) << 2;
                af[ms][0] = As[mm * 32 + (kk ^ sw)];
                af[ms][1] = As[(mm + 8) * 32 + (kk ^ sw)];
                af[ms][2] = As[mm * 32 + ((kk + 4) ^ sw)];
                af[ms][3] = As[(mm + 8) * 32 + ((kk + 4) ^ sw)];
            }
#pragma unroll
            for (int ns = 0; ns < 4; ++ns) {
                int nn = wn0 + ns * 8 + g;
                int sw = (g) << 2;
                bf[ns][0] = Bs[nn * 32 + (kk ^ sw)];
                bf[ns][1] = Bs[nn * 32 + ((kk + 4) ^ sw)];
            }
#pragma unroll
            for (int ms = 0; ms < 4; ++ms)
#pragma unroll
                for (int ns = 0; ns < 4; ++ns)
                    mma_tf32(acc[ms][ns], af[ms], bf[ns]);
        }
        __syncthreads();
    }

    // epilogue: D rows g/g+8, cols 2*tig, 2*tig+1 per 16x8 sub-tile
    float* Cb = C + (size_t)bz * batchC;
    const float gm = resid ? gamma[0] : 0.f;
#pragma unroll
    for (int ms = 0; ms < 4; ++ms) {
        int ma = m0 + wm0 + ms * 16 + g;
        int mb = ma + 8;
        float bia = bias ? bias[ma] : 0.f;
        float bib = bias ? bias[mb] : 0.f;
        float* cpa = Cb + (size_t)ma * N;
        float* cpb = Cb + (size_t)mb * N;
        const float* rpa = resid ? (resid + (size_t)bz * batchR + (size_t)ma * N) : nullptr;
        const float* rpb = resid ? (resid + (size_t)bz * batchR + (size_t)mb * N) : nullptr;
#pragma unroll
        for (int ns = 0; ns < 4; ++ns) {
            int n = n0 + wn0 + ns * 8 + tig * 2;
            float v0 = acc[ms][ns][0] + bia;
            float v1 = acc[ms][ns][1] + bia;
            float v2 = acc[ms][ns][2] + bib;
            float v3 = acc[ms][ns][3] + bib;
            if (resid) {
                v0 = gm * v0 + rpa[n];
                v1 = gm * v1 + rpa[n + 1];
                v2 = gm * v2 + rpb[n];
                v3 = gm * v3 + rpb[n + 1];
            }
            cpa[n]     = v0;
            cpa[n + 1] = v1;
            cpb[n]     = v2;
            cpb[n + 1] = v3;
        }
    }
}

// ---------------- row softmax over 2304 columns ----------------------------------
__global__ void softmax_rows(float* __restrict__ attn)
{
    __shared__ float red[8];
    const size_t row = blockIdx.x;
    float* p = attn + row * (size_t)NPIX;
    const int tid = threadIdx.x;
    const int lane = tid & 31, wid = tid >> 5;

    float v[9];
    float mx = -3.4e38f;
#pragma unroll
    for (int i = 0; i < 9; ++i) {
        v[i] = p[tid + i * 256];
        mx = fmaxf(mx, v[i]);
    }
#pragma unroll
    for (int o = 16; o > 0; o >>= 1) mx = fmaxf(mx, __shfl_xor_sync(0xffffffffu, mx, o));
    if (lane == 0) red[wid] = mx;
    __syncthreads();
    mx = red[0];
#pragma unroll
    for (int i = 1; i < 8; ++i) mx = fmaxf(mx, red[i]);
    __syncthreads();

    float s = 0.f;
#pragma unroll
    for (int i = 0; i < 9; ++i) {
        v[i] = __expf(v[i] - mx);
        s += v[i];
    }
#pragma unroll
    for (int o = 16; o > 0; o >>= 1) s += __shfl_xor_sync(0xffffffffu, s, o);
    if (lane == 0) red[wid] = s;
    __syncthreads();
    s = 0.f;
#pragma unroll
    for (int i = 0; i < 8; ++i) s += red[i];
    const float inv = 1.f / s;
#pragma unroll
    for (int i = 0; i < 9; ++i) p[tid + i * 256] = v[i] * inv;
}

// ---------------- launcher -------------------------------------------------------
extern "C" void kernel_launch(void* const* d_in, const int* in_sizes, int n_in,
                              void* d_out, int out_size)
{
    const float* x     = (const float*)d_in[0];
    const float* w_pre = (const float*)d_in[1];
    const float* b_pre = (const float*)d_in[2];
    const float* bn1g  = (const float*)d_in[3];
    const float* bn1b  = (const float*)d_in[4];
    const float* bn1m  = (const float*)d_in[5];
    const float* bn1v  = (const float*)d_in[6];
    const float* w_q   = (const float*)d_in[7];
    const float* b_q   = (const float*)d_in[8];
    const float* w_k   = (const float*)d_in[9];
    const float* b_k   = (const float*)d_in[10];
    const float* w_v   = (const float*)d_in[11];
    const float* b_v   = (const float*)d_in[12];
    const float* w_f   = (const float*)d_in[13];
    const float* b_f   = (const float*)d_in[14];
    const float* bn2g  = (const float*)d_in[15];
    const float* bn2b  = (const float*)d_in[16];
    const float* bn2m  = (const float*)d_in[17];
    const float* bn2v  = (const float*)d_in[18];
    const float* gamma = (const float*)d_in[19];
    float* out = (float*)d_out;

    float *x1, *q, *k, *v, *of, *attn;
    cudaGetSymbolAddress((void**)&x1,   g_x1);
    cudaGetSymbolAddress((void**)&q,    g_q);
    cudaGetSymbolAddress((void**)&k,    g_k);
    cudaGetSymbolAddress((void**)&v,    g_v);
    cudaGetSymbolAddress((void**)&of,   g_of);
    cudaGetSymbolAddress((void**)&attn, g_attn);

    const long long bX1 = (long long)CC * NPIX;
    const long long bQK = (long long)CR * NPIX;
    const long long bAT = (long long)NPIX * NPIX;

    // 1) conv1 + BN + ReLU  -> x1  (fp32, precision anchor)
    conv3x3_bn_relu<CIN1><<<dim3(CC / 8, BB), 256>>>(x, w_pre, b_pre, bn1g, bn1b, bn1m, bn1v, x1);

    // 2) q/k projections: fp32 (feed the softmax-sensitive energy path)
    gemmT<64, 128><<<dim3(NPIX / 128, CR / 64, BB), 256>>>(
        w_q, 0, CC, 1, x1, bX1, NPIX, 1, q, bQK, CR, NPIX, CC, b_q, nullptr, 0, nullptr);
    gemmT<64, 128><<<dim3(NPIX / 128, CR / 64, BB), 256>>>(
        w_k, 0, CC, 1, x1, bX1, NPIX, 1, k, bQK, CR, NPIX, CC, b_k, nullptr, 0, nullptr);
    // v projection: tf32 tensor cores (tolerant path)
    gemm_tf32<<<dim3(NPIX / 128, CC / 128, BB), 256>>>(
        w_v, 0, CC, x1, bX1, NPIX, 1, v, bX1, CC, NPIX, CC, b_v, nullptr, 0, nullptr);

    // 3-5) attention in chunks of CHUNK batches
    for (int c0 = 0; c0 < BB; c0 += CHUNK) {
        const float* qb = q  + (size_t)c0 * bQK;
        const float* kb = k  + (size_t)c0 * bQK;
        const float* vb = v  + (size_t)c0 * bX1;
        const float* xb = x1 + (size_t)c0 * bX1;
        float*       ob = of + (size_t)c0 * bX1;

        // energy: fp32 (softmax sensitivity)
        gemmT<128, 128><<<dim3(NPIX / 128, NPIX / 128, CHUNK), 256>>>(
            qb, bQK, 1, NPIX, kb, bQK, NPIX, 1,
            attn, bAT, NPIX, NPIX, CR, nullptr, nullptr, 0, nullptr);

        softmax_rows<<<CHUNK * NPIX, 256>>>(attn);

        // attn*V + residual: tf32 tensor cores
        // A = v (k-contiguous: v[c][j], Am=NPIX), B = attn (k-contiguous: Bk=1, Bn=NPIX)
        gemm_tf32<<<dim3(NPIX / 128, CC / 128, CHUNK), 256>>>(
            vb, bX1, NPIX, attn, bAT, 1, NPIX,
            ob, bX1, CC, NPIX, NPIX, nullptr, xb, bX1, gamma);
    }

    // 6) conv2 + BN + ReLU -> d_out (fp32)
    conv3x3_bn_relu<CC><<<dim3(CC / 8, BB), 256>>>(of, w_f, b_f, bn2g, bn2b, bn2m, bn2v, out);
}

// round 10
// speedup vs baseline: 3.0101x; 2.0866x over previous
#include <cuda_runtime.h>
#include <math.h>
#include <stdint.h>

// Problem constants
#define BB    8
#define CIN1  512
#define CC    256
#define HH    48
#define WW    48
#define NPIX  2304      // 48*48
#define CR    64        // C/r
#define EPSBN 1e-5f
#define CHUNK 4         // attention batches processed per chunk

// ---------------- scratch (static device globals; ~151 MB total) ----------------
__device__ float g_x1  [(size_t)BB * CC * NPIX];
__device__ float g_q   [(size_t)BB * CR * NPIX];
__device__ float g_k   [(size_t)BB * CR * NPIX];
__device__ float g_v   [(size_t)BB * CC * NPIX];
__device__ float g_of  [(size_t)BB * CC * NPIX];
__device__ float g_attn[(size_t)CHUNK * NPIX * NPIX];

// ---------------- tf32 helpers ----------------------------------------------------
__device__ __forceinline__ uint32_t f2tf32(float f) {
    uint32_t r;
    asm("cvt.rna.tf32.f32 %0, %1;" : "=r"(r) : "f"(f));
    return r;
}
__device__ __forceinline__ void mma_tf32(float* d, const uint32_t* a, const uint32_t* b) {
    asm volatile(
        "mma.sync.aligned.m16n8k8.row.col.f32.tf32.tf32.f32 "
        "{%0,%1,%2,%3}, {%4,%5,%6,%7}, {%8,%9}, {%0,%1,%2,%3};"
        : "+f"(d[0]), "+f"(d[1]), "+f"(d[2]), "+f"(d[3])
        : "r"(a[0]), "r"(a[1]), "r"(a[2]), "r"(a[3]), "r"(b[0]), "r"(b[1]));
}

// ---------------- conv3x3 (pad=1) + BN + ReLU as implicit GEMM, 3xTF32 ------------
// Out[co, p] = relu(bn(sum_{cin,tap} W[co, cin*9+tap] * X[cin, p + off(tap)] + bias))
// Tile 128(co) x 128(pix), K-chunk 16, 256 threads = 8 warps (2M x 4N), warp 64x32.
// 3xTF32: acc += hi*hi + hi*lo + lo*hi  (error ~fp32).
__global__ void __launch_bounds__(256) conv3x3_tc(
        const float* __restrict__ X,      // [B, CIN, NPIX]
        const float* __restrict__ W,      // [256, CIN*9] (OIHW flattened)
        const float* __restrict__ bconv,
        const float* __restrict__ bg,
        const float* __restrict__ bb,
        const float* __restrict__ bm,
        const float* __restrict__ bv,
        float* __restrict__ out,          // [B, 256, NPIX]
        int CIN)
{
    __shared__ uint32_t As_hi[128 * 16];
    __shared__ uint32_t As_lo[128 * 16];
    __shared__ uint32_t Bs_hi[128 * 16];
    __shared__ uint32_t Bs_lo[128 * 16];

    const int bz = blockIdx.z;
    const int K9 = CIN * 9;
    const float* Xb = X + (size_t)bz * CIN * NPIX;
    const int m0 = blockIdx.y * 128, p0 = blockIdx.x * 128;

    const int tid  = threadIdx.x;
    const int wid  = tid >> 5, lane = tid & 31;
    const int g    = lane >> 2, tig = lane & 3;
    const int wm0  = (wid & 1) * 64;
    const int wn0  = (wid >> 1) * 32;

    // loop-invariant staging coords
    const int a_kk = tid & 15;           // A: column fixed per thread
    const int a_m  = tid >> 4;           // A: row base (+16 per step)
    const int b_nn = tid & 127;          // B: pixel fixed per thread
    const int b_k  = tid >> 7;           // B: k base (+2 per step)
    const int p    = p0 + b_nn;
    const int prow = p / 48;
    const int pcol = p - prow * 48;

    float acc[4][4][4];
#pragma unroll
    for (int i = 0; i < 4; ++i)
#pragma unroll
        for (int j = 0; j < 4; ++j)
#pragma unroll
            for (int c = 0; c < 4; ++c) acc[i][j][c] = 0.f;

    for (int k0 = 0; k0 < K9; k0 += 16) {
        // ---- stage A (weights, k-contiguous): 2048 elems, 8 per thread
#pragma unroll
        for (int t = 0; t < 8; ++t) {
            int mm = a_m + t * 16;
            float v = W[(size_t)(m0 + mm) * K9 + (k0 + a_kk)];
            uint32_t hi = f2tf32(v);
            float lo = v - __uint_as_float(hi);
            int idx = mm * 16 + (a_kk ^ ((mm & 7) << 1));
            As_hi[idx] = hi;
            As_lo[idx] = f2tf32(lo);
        }
        // ---- stage B (im2col gather): 2048 elems, 8 per thread
#pragma unroll
        for (int t = 0; t < 8; ++t) {
            int kk = b_k + t * 2;
            int k  = k0 + kk;
            int cin = k / 9;
            int tap = k - cin * 9;
            int t3  = tap / 3;
            int rr  = prow + t3 - 1;
            int cc  = pcol + (tap - t3 * 3) - 1;
            float v = 0.f;
            if ((unsigned)rr < 48u && (unsigned)cc < 48u)
                v = Xb[(size_t)cin * NPIX + rr * 48 + cc];
            uint32_t hi = f2tf32(v);
            float lo = v - __uint_as_float(hi);
            int idx = b_nn * 16 + (kk ^ ((b_nn & 7) << 1));
            Bs_hi[idx] = hi;
            Bs_lo[idx] = f2tf32(lo);
        }
        __syncthreads();

#pragma unroll
        for (int ks = 0; ks < 2; ++ks) {
            const int kk = ks * 8 + tig;
            const int sw = g << 1;
            uint32_t ah[4][4], al[4][4], bh[4][2], bl[4][2];
#pragma unroll
            for (int ms = 0; ms < 4; ++ms) {
                int mm = wm0 + ms * 16 + g;
                int i0 = mm * 16 + (kk ^ sw);
                int i1 = (mm + 8) * 16 + (kk ^ sw);
                int i2 = mm * 16 + ((kk + 4) ^ sw);
                int i3 = (mm + 8) * 16 + ((kk + 4) ^ sw);
                ah[ms][0] = As_hi[i0]; ah[ms][1] = As_hi[i1];
                ah[ms][2] = As_hi[i2]; ah[ms][3] = As_hi[i3];
                al[ms][0] = As_lo[i0]; al[ms][1] = As_lo[i1];
                al[ms][2] = As_lo[i2]; al[ms][3] = As_lo[i3];
            }
#pragma unroll
            for (int ns = 0; ns < 4; ++ns) {
                int nn = wn0 + ns * 8 + g;
                int i0 = nn * 16 + (kk ^ sw);
                int i1 = nn * 16 + ((kk + 4) ^ sw);
                bh[ns][0] = Bs_hi[i0]; bh[ns][1] = Bs_hi[i1];
                bl[ns][0] = Bs_lo[i0]; bl[ns][1] = Bs_lo[i1];
            }
#pragma unroll
            for (int ms = 0; ms < 4; ++ms)
#pragma unroll
                for (int ns = 0; ns < 4; ++ns) {
                    mma_tf32(acc[ms][ns], ah[ms], bh[ns]);
                    mma_tf32(acc[ms][ns], ah[ms], bl[ns]);
                    mma_tf32(acc[ms][ns], al[ms], bh[ns]);
                }
        }
        __syncthreads();
    }

    // ---- epilogue: conv bias + BN + ReLU
    float* Ob = out + (size_t)bz * CC * NPIX;
#pragma unroll
    for (int ms = 0; ms < 4; ++ms) {
        int ma = m0 + wm0 + ms * 16 + g;
        int mb = ma + 8;
        float sca = bg[ma] * rsqrtf(bv[ma] + EPSBN);
        float scb = bg[mb] * rsqrtf(bv[mb] + EPSBN);
        float sha = bb[ma] - bm[ma] * sca + bconv[ma] * sca;
        float shb = bb[mb] - bm[mb] * scb + bconv[mb] * scb;
        float* cpa = Ob + (size_t)ma * NPIX;
        float* cpb = Ob + (size_t)mb * NPIX;
#pragma unroll
        for (int ns = 0; ns < 4; ++ns) {
            int n = p0 + wn0 + ns * 8 + tig * 2;
            cpa[n]     = fmaxf(acc[ms][ns][0] * sca + sha, 0.f);
            cpa[n + 1] = fmaxf(acc[ms][ns][1] * sca + sha, 0.f);
            cpb[n]     = fmaxf(acc[ms][ns][2] * scb + shb, 0.f);
            cpb[n + 1] = fmaxf(acc[ms][ns][3] * scb + shb, 0.f);
        }
    }
}

// ---------------- fp32 tiled SGEMM (precision-critical path: q/k/energy) ---------
template<int TM, int TN>
__global__ void __launch_bounds__(256) gemmT(
        const float* __restrict__ A, long long batchA, int Am, int Ak,
        const float* __restrict__ B, long long batchB, int Bk, int Bn,
        float* __restrict__ C, long long batchC,
        int M, int N, int K,
        const float* __restrict__ bias,
        const float* __restrict__ resid, long long batchR,
        const float* __restrict__ gamma)
{
    constexpr int RM = TM / 16;
    constexpr int RN = TN / 16;
    __shared__ float As[16][TM];
    __shared__ float Bs[16][TN];

    const int bz = blockIdx.z;
    const float* Ab = A + (size_t)bz * batchA;
    const float* Bb = B + (size_t)bz * batchB;
    const int m0 = blockIdx.y * TM, n0 = blockIdx.x * TN;
    const int tid = threadIdx.x;
    const int tx = tid & 15, ty = tid >> 4;

    float acc[RM][RN];
#pragma unroll
    for (int i = 0; i < RM; ++i)
#pragma unroll
        for (int j = 0; j < RN; ++j) acc[i][j] = 0.f;

    for (int k0 = 0; k0 < K; k0 += 16) {
        if (Ak == 1) {
#pragma unroll
            for (int i = tid; i < TM * 16; i += 256) {
                int kk = i & 15, mm = i >> 4;
                As[kk][mm] = Ab[(size_t)(m0 + mm) * Am + (k0 + kk)];
            }
        } else {
#pragma unroll
            for (int i = tid; i < TM * 16; i += 256) {
                int mm = i % TM, kk = i / TM;
                As[kk][mm] = Ab[(size_t)(m0 + mm) * Am + (size_t)(k0 + kk) * Ak];
            }
        }
        if (Bk == 1) {
#pragma unroll
            for (int i = tid; i < TN * 16; i += 256) {
                int kk = i & 15, nn = i >> 4;
                Bs[kk][nn] = Bb[(size_t)(k0 + kk) + (size_t)(n0 + nn) * Bn];
            }
        } else {
#pragma unroll
            for (int i = tid; i < TN * 16; i += 256) {
                int nn = i % TN, kk = i / TN;
                Bs[kk][nn] = Bb[(size_t)(k0 + kk) * Bk + (size_t)(n0 + nn) * Bn];
            }
        }
        __syncthreads();

#pragma unroll
        for (int kk = 0; kk < 16; ++kk) {
            float a[RM], bv[RN];
#pragma unroll
            for (int i = 0; i < RM; ++i) a[i] = As[kk][ty * RM + i];
#pragma unroll
            for (int j = 0; j < RN; ++j) bv[j] = Bs[kk][tx * RN + j];
#pragma unroll
            for (int i = 0; i < RM; ++i)
#pragma unroll
                for (int j = 0; j < RN; ++j) acc[i][j] += a[i] * bv[j];
        }
        __syncthreads();
    }

    float* Cb = C + (size_t)bz * batchC;
    const float gm = resid ? gamma[0] : 0.f;
#pragma unroll
    for (int i = 0; i < RM; ++i) {
        int m = m0 + ty * RM + i;
        float bi = bias ? bias[m] : 0.f;
        const float* rp = resid ? (resid + (size_t)bz * batchR + (size_t)m * N) : nullptr;
        float* cp = Cb + (size_t)m * N;
#pragma unroll
        for (int j = 0; j < RN; ++j) {
            int n = n0 + tx * RN + j;
            float v = acc[i][j] + bi;
            if (rp) v = gm * v + rp[n];
            cp[n] = v;
        }
    }
}

// ---------------- tf32 tensor-core GEMM (tolerant path: v-proj, attn*V) ----------
__global__ void __launch_bounds__(256) gemm_tf32(
        const float* __restrict__ A, long long batchA, int Am,
        const float* __restrict__ B, long long batchB, int Bk, int Bn,
        float* __restrict__ C, long long batchC,
        int M, int N, int K,
        const float* __restrict__ bias,
        const float* __restrict__ resid, long long batchR,
        const float* __restrict__ gamma)
{
    __shared__ uint32_t As[128 * 32];
    __shared__ uint32_t Bs[128 * 32];

    const int bz  = blockIdx.z;
    const float* Ab = A + (size_t)bz * batchA;
    const float* Bb = B + (size_t)bz * batchB;
    const int m0 = blockIdx.y * 128, n0 = blockIdx.x * 128;
    const int tid  = threadIdx.x;
    const int wid  = tid >> 5, lane = tid & 31;
    const int g    = lane >> 2, tig = lane & 3;
    const int wm0  = (wid & 1) * 64;
    const int wn0  = (wid >> 1) * 32;

    float acc[4][4][4];
#pragma unroll
    for (int i = 0; i < 4; ++i)
#pragma unroll
        for (int j = 0; j < 4; ++j)
#pragma unroll
            for (int c = 0; c < 4; ++c) acc[i][j][c] = 0.f;

    for (int k0 = 0; k0 < K; k0 += 32) {
#pragma unroll
        for (int i = tid; i < 4096; i += 256) {
            int kk = i & 31, mm = i >> 5;
            As[mm * 32 + (kk ^ ((mm & 7) << 2))] =
                f2tf32(Ab[(size_t)(m0 + mm) * Am + (k0 + kk)]);
        }
        if (Bk == 1) {
#pragma unroll
            for (int i = tid; i < 4096; i += 256) {
                int kk = i & 31, nn = i >> 5;
                Bs[nn * 32 + (kk ^ ((nn & 7) << 2))] =
                    f2tf32(Bb[(size_t)(k0 + kk) + (size_t)(n0 + nn) * Bn]);
            }
        } else {
#pragma unroll
            for (int i = tid; i < 4096; i += 256) {
                int nn = i & 127, kk = i >> 7;
                Bs[nn * 32 + (kk ^ ((nn & 7) << 2))] =
                    f2tf32(Bb[(size_t)(k0 + kk) * Bk + (n0 + nn)]);
            }
        }
        __syncthreads();

#pragma unroll
        for (int ks = 0; ks < 4; ++ks) {
            const int kk = ks * 8 + tig;
            uint32_t af[4][4], bf[4][2];
#pragma unroll
            for (int ms = 0; ms < 4; ++ms) {
                int mm = wm0 + ms * 16 + g;
                int sw = g << 2;
                af[ms][0] = As[mm * 32 + (kk ^ sw)];
                af[ms][1] = As[(mm + 8) * 32 + (kk ^ sw)];
                af[ms][2] = As[mm * 32 + ((kk + 4) ^ sw)];
                af[ms][3] = As[(mm + 8) * 32 + ((kk + 4) ^ sw)];
            }
#pragma unroll
            for (int ns = 0; ns < 4; ++ns) {
                int nn = wn0 + ns * 8 + g;
                int sw = g << 2;
                bf[ns][0] = Bs[nn * 32 + (kk ^ sw)];
                bf[ns][1] = Bs[nn * 32 + ((kk + 4) ^ sw)];
            }
#pragma unroll
            for (int ms = 0; ms < 4; ++ms)
#pragma unroll
                for (int ns = 0; ns < 4; ++ns)
                    mma_tf32(acc[ms][ns], af[ms], bf[ns]);
        }
        __syncthreads();
    }

    float* Cb = C + (size_t)bz * batchC;
    const float gm = resid ? gamma[0] : 0.f;
#pragma unroll
    for (int ms = 0; ms < 4; ++ms) {
        int ma = m0 + wm0 + ms * 16 + g;
        int mb = ma + 8;
        float bia = bias ? bias[ma] : 0.f;
        float bib = bias ? bias[mb] : 0.f;
        float* cpa = Cb + (size_t)ma * N;
        float* cpb = Cb + (size_t)mb * N;
        const float* rpa = resid ? (resid + (size_t)bz * batchR + (size_t)ma * N) : nullptr;
        const float* rpb = resid ? (resid + (size_t)bz * batchR + (size_t)mb * N) : nullptr;
#pragma unroll
        for (int ns = 0; ns < 4; ++ns) {
            int n = n0 + wn0 + ns * 8 + tig * 2;
            float v0 = acc[ms][ns][0] + bia;
            float v1 = acc[ms][ns][1] + bia;
            float v2 = acc[ms][ns][2] + bib;
            float v3 = acc[ms][ns][3] + bib;
            if (resid) {
                v0 = gm * v0 + rpa[n];
                v1 = gm * v1 + rpa[n + 1];
                v2 = gm * v2 + rpb[n];
                v3 = gm * v3 + rpb[n + 1];
            }
            cpa[n]     = v0;
            cpa[n + 1] = v1;
            cpb[n]     = v2;
            cpb[n + 1] = v3;
        }
    }
}

// ---------------- row softmax over 2304 columns ----------------------------------
__global__ void softmax_rows(float* __restrict__ attn)
{
    __shared__ float red[8];
    const size_t row = blockIdx.x;
    float* p = attn + row * (size_t)NPIX;
    const int tid = threadIdx.x;
    const int lane = tid & 31, wid = tid >> 5;

    float v[9];
    float mx = -3.4e38f;
#pragma unroll
    for (int i = 0; i < 9; ++i) {
        v[i] = p[tid + i * 256];
        mx = fmaxf(mx, v[i]);
    }
#pragma unroll
    for (int o = 16; o > 0; o >>= 1) mx = fmaxf(mx, __shfl_xor_sync(0xffffffffu, mx, o));
    if (lane == 0) red[wid] = mx;
    __syncthreads();
    mx = red[0];
#pragma unroll
    for (int i = 1; i < 8; ++i) mx = fmaxf(mx, red[i]);
    __syncthreads();

    float s = 0.f;
#pragma unroll
    for (int i = 0; i < 9; ++i) {
        v[i] = __expf(v[i] - mx);
        s += v[i];
    }
#pragma unroll
    for (int o = 16; o > 0; o >>= 1) s += __shfl_xor_sync(0xffffffffu, s, o);
    if (lane == 0) red[wid] = s;
    __syncthreads();
    s = 0.f;
#pragma unroll
    for (int i = 0; i < 8; ++i) s += red[i];
    const float inv = 1.f / s;
#pragma unroll
    for (int i = 0; i < 9; ++i) p[tid + i * 256] = v[i] * inv;
}

// ---------------- launcher -------------------------------------------------------
extern "C" void kernel_launch(void* const* d_in, const int* in_sizes, int n_in,
                              void* d_out, int out_size)
{
    const float* x     = (const float*)d_in[0];
    const float* w_pre = (const float*)d_in[1];
    const float* b_pre = (const float*)d_in[2];
    const float* bn1g  = (const float*)d_in[3];
    const float* bn1b  = (const float*)d_in[4];
    const float* bn1m  = (const float*)d_in[5];
    const float* bn1v  = (const float*)d_in[6];
    const float* w_q   = (const float*)d_in[7];
    const float* b_q   = (const float*)d_in[8];
    const float* w_k   = (const float*)d_in[9];
    const float* b_k   = (const float*)d_in[10];
    const float* w_v   = (const float*)d_in[11];
    const float* b_v   = (const float*)d_in[12];
    const float* w_f   = (const float*)d_in[13];
    const float* b_f   = (const float*)d_in[14];
    const float* bn2g  = (const float*)d_in[15];
    const float* bn2b  = (const float*)d_in[16];
    const float* bn2m  = (const float*)d_in[17];
    const float* bn2v  = (const float*)d_in[18];
    const float* gamma = (const float*)d_in[19];
    float* out = (float*)d_out;

    float *x1, *q, *k, *v, *of, *attn;
    cudaGetSymbolAddress((void**)&x1,   g_x1);
    cudaGetSymbolAddress((void**)&q,    g_q);
    cudaGetSymbolAddress((void**)&k,    g_k);
    cudaGetSymbolAddress((void**)&v,    g_v);
    cudaGetSymbolAddress((void**)&of,   g_of);
    cudaGetSymbolAddress((void**)&attn, g_attn);

    const long long bX1 = (long long)CC * NPIX;
    const long long bQK = (long long)CR * NPIX;
    const long long bAT = (long long)NPIX * NPIX;

    // 1) conv1 + BN + ReLU -> x1  (3xTF32 tensor cores, ~fp32 accuracy)
    conv3x3_tc<<<dim3(NPIX / 128, 2, BB), 256>>>(
        x, w_pre, b_pre, bn1g, bn1b, bn1m, bn1v, x1, CIN1);

    // 2) q/k projections: fp32 (feed the softmax-sensitive energy path)
    gemmT<64, 128><<<dim3(NPIX / 128, CR / 64, BB), 256>>>(
        w_q, 0, CC, 1, x1, bX1, NPIX, 1, q, bQK, CR, NPIX, CC, b_q, nullptr, 0, nullptr);
    gemmT<64, 128><<<dim3(NPIX / 128, CR / 64, BB), 256>>>(
        w_k, 0, CC, 1, x1, bX1, NPIX, 1, k, bQK, CR, NPIX, CC, b_k, nullptr, 0, nullptr);
    // v projection: tf32 tensor cores (tolerant path)
    gemm_tf32<<<dim3(NPIX / 128, CC / 128, BB), 256>>>(
        w_v, 0, CC, x1, bX1, NPIX, 1, v, bX1, CC, NPIX, CC, b_v, nullptr, 0, nullptr);

    // 3-5) attention in chunks of CHUNK batches
    for (int c0 = 0; c0 < BB; c0 += CHUNK) {
        const float* qb = q  + (size_t)c0 * bQK;
        const float* kb = k  + (size_t)c0 * bQK;
        const float* vb = v  + (size_t)c0 * bX1;
        const float* xb = x1 + (size_t)c0 * bX1;
        float*       ob = of + (size_t)c0 * bX1;

        // energy: fp32 (softmax sensitivity)
        gemmT<128, 128><<<dim3(NPIX / 128, NPIX / 128, CHUNK), 256>>>(
            qb, bQK, 1, NPIX, kb, bQK, NPIX, 1,
            attn, bAT, NPIX, NPIX, CR, nullptr, nullptr, 0, nullptr);

        softmax_rows<<<CHUNK * NPIX, 256>>>(attn);

        // attn*V + residual: tf32 tensor cores
        gemm_tf32<<<dim3(NPIX / 128, CC / 128, CHUNK), 256>>>(
            vb, bX1, NPIX, attn, bAT, 1, NPIX,
            ob, bX1, CC, NPIX, NPIX, nullptr, xb, bX1, gamma);
    }

    // 6) conv2 + BN + ReLU -> d_out (3xTF32 tensor cores)
    conv3x3_tc<<<dim3(NPIX / 128, 2, BB), 256>>>(
        of, w_f, b_f, bn2g, bn2b, bn2m, bn2v, out, CC);
}

// round 11
// speedup vs baseline: 3.6692x; 1.2190x over previous
#include <cuda_runtime.h>
#include <math.h>
#include <stdint.h>

// Problem constants
#define BB    8
#define CIN1  512
#define CC    256
#define HH    48
#define WW    48
#define NPIX  2304      // 48*48
#define CR    64        // C/r
#define EPSBN 1e-5f
#define CHUNK 4         // attention batches processed per chunk

// ---------------- scratch (static device globals; ~151 MB total) ----------------
__device__ float g_x1  [(size_t)BB * CC * NPIX];
__device__ float g_q   [(size_t)BB * CR * NPIX];
__device__ float g_k   [(size_t)BB * CR * NPIX];
__device__ float g_v   [(size_t)BB * CC * NPIX];
__device__ float g_of  [(size_t)BB * CC * NPIX];
__device__ float g_attn[(size_t)CHUNK * NPIX * NPIX];

// ---------------- tf32 helpers ----------------------------------------------------
__device__ __forceinline__ uint32_t f2tf32(float f) {
    uint32_t r;
    asm("cvt.rna.tf32.f32 %0, %1;" : "=r"(r) : "f"(f));
    return r;
}
__device__ __forceinline__ void mma_tf32(float* d, const uint32_t* a, const uint32_t* b) {
    asm volatile(
        "mma.sync.aligned.m16n8k8.row.col.f32.tf32.tf32.f32 "
        "{%0,%1,%2,%3}, {%4,%5,%6,%7}, {%8,%9}, {%0,%1,%2,%3};"
        : "+f"(d[0]), "+f"(d[1]), "+f"(d[2]), "+f"(d[3])
        : "r"(a[0]), "r"(a[1]), "r"(a[2]), "r"(a[3]), "r"(b[0]), "r"(b[1]));
}

// ---------------- conv3x3 (pad=1) + BN + ReLU as implicit GEMM, 3xTF32 ------------
// Register-prefetch double-buffered: chunk k+1's LDGs issue while chunk k computes.
__global__ void __launch_bounds__(256) conv3x3_tc(
        const float* __restrict__ X,      // [B, CIN, NPIX]
        const float* __restrict__ W,      // [256, CIN*9] (OIHW flattened)
        const float* __restrict__ bconv,
        const float* __restrict__ bg,
        const float* __restrict__ bb,
        const float* __restrict__ bm,
        const float* __restrict__ bv,
        float* __restrict__ out,          // [B, 256, NPIX]
        int CIN)
{
    __shared__ uint32_t As_hi[128 * 16];
    __shared__ uint32_t As_lo[128 * 16];
    __shared__ uint32_t Bs_hi[128 * 16];
    __shared__ uint32_t Bs_lo[128 * 16];

    const int bz = blockIdx.z;
    const int K9 = CIN * 9;
    const float* Xb = X + (size_t)bz * CIN * NPIX;
    const int m0 = blockIdx.y * 128, p0 = blockIdx.x * 128;

    const int tid  = threadIdx.x;
    const int wid  = tid >> 5, lane = tid & 31;
    const int g    = lane >> 2, tig = lane & 3;
    const int wm0  = (wid & 1) * 64;
    const int wn0  = (wid >> 1) * 32;

    const int a_kk = tid & 15;
    const int a_m  = tid >> 4;
    const int b_nn = tid & 127;
    const int b_k  = tid >> 7;
    const int p    = p0 + b_nn;
    const int prow = p / 48;
    const int pcol = p - prow * 48;

    float acc[4][4][4];
#pragma unroll
    for (int i = 0; i < 4; ++i)
#pragma unroll
        for (int j = 0; j < 4; ++j)
#pragma unroll
            for (int c = 0; c < 4; ++c) acc[i][j][c] = 0.f;

    float apre[8], bpre[8];
    // prefetch chunk 0
#pragma unroll
    for (int t = 0; t < 8; ++t)
        apre[t] = W[(size_t)(m0 + a_m + t * 16) * K9 + a_kk];
#pragma unroll
    for (int t = 0; t < 8; ++t) {
        int k   = b_k + t * 2;
        int cin = k / 9;
        int tap = k - cin * 9;
        int t3  = tap / 3;
        int rr  = prow + t3 - 1;
        int cc  = pcol + (tap - t3 * 3) - 1;
        float v = 0.f;
        if ((unsigned)rr < 48u && (unsigned)cc < 48u)
            v = Xb[(size_t)cin * NPIX + rr * 48 + cc];
        bpre[t] = v;
    }

    for (int k0 = 0; k0 < K9; k0 += 16) {
        // ---- split + store current chunk
#pragma unroll
        for (int t = 0; t < 8; ++t) {
            int mm  = a_m + t * 16;
            float v = apre[t];
            uint32_t hi = f2tf32(v);
            int idx = mm * 16 + (a_kk ^ ((mm & 7) << 1));
            As_hi[idx] = hi;
            As_lo[idx] = f2tf32(v - __uint_as_float(hi));
        }
#pragma unroll
        for (int t = 0; t < 8; ++t) {
            int kk  = b_k + t * 2;
            float v = bpre[t];
            uint32_t hi = f2tf32(v);
            int idx = b_nn * 16 + (kk ^ ((b_nn & 7) << 1));
            Bs_hi[idx] = hi;
            Bs_lo[idx] = f2tf32(v - __uint_as_float(hi));
        }
        __syncthreads();

        // ---- prefetch next chunk (LDGs overlap the MMA loop below)
        if (k0 + 16 < K9) {
#pragma unroll
            for (int t = 0; t < 8; ++t)
                apre[t] = W[(size_t)(m0 + a_m + t * 16) * K9 + (k0 + 16 + a_kk)];
#pragma unroll
            for (int t = 0; t < 8; ++t) {
                int k   = k0 + 16 + b_k + t * 2;
                int cin = k / 9;
                int tap = k - cin * 9;
                int t3  = tap / 3;
                int rr  = prow + t3 - 1;
                int cc  = pcol + (tap - t3 * 3) - 1;
                float v = 0.f;
                if ((unsigned)rr < 48u && (unsigned)cc < 48u)
                    v = Xb[(size_t)cin * NPIX + rr * 48 + cc];
                bpre[t] = v;
            }
        }

        // ---- compute
#pragma unroll
        for (int ks = 0; ks < 2; ++ks) {
            const int kk = ks * 8 + tig;
            const int sw = g << 1;
            uint32_t ah[4][4], al[4][4], bh[4][2], bl[4][2];
#pragma unroll
            for (int ms = 0; ms < 4; ++ms) {
                int mm = wm0 + ms * 16 + g;
                int i0 = mm * 16 + (kk ^ sw);
                int i1 = (mm + 8) * 16 + (kk ^ sw);
                int i2 = mm * 16 + ((kk + 4) ^ sw);
                int i3 = (mm + 8) * 16 + ((kk + 4) ^ sw);
                ah[ms][0] = As_hi[i0]; ah[ms][1] = As_hi[i1];
                ah[ms][2] = As_hi[i2]; ah[ms][3] = As_hi[i3];
                al[ms][0] = As_lo[i0]; al[ms][1] = As_lo[i1];
                al[ms][2] = As_lo[i2]; al[ms][3] = As_lo[i3];
            }
#pragma unroll
            for (int ns = 0; ns < 4; ++ns) {
                int nn = wn0 + ns * 8 + g;
                int i0 = nn * 16 + (kk ^ sw);
                int i1 = nn * 16 + ((kk + 4) ^ sw);
                bh[ns][0] = Bs_hi[i0]; bh[ns][1] = Bs_hi[i1];
                bl[ns][0] = Bs_lo[i0]; bl[ns][1] = Bs_lo[i1];
            }
#pragma unroll
            for (int ms = 0; ms < 4; ++ms)
#pragma unroll
                for (int ns = 0; ns < 4; ++ns) {
                    mma_tf32(acc[ms][ns], ah[ms], bh[ns]);
                    mma_tf32(acc[ms][ns], ah[ms], bl[ns]);
                    mma_tf32(acc[ms][ns], al[ms], bh[ns]);
                }
        }
        __syncthreads();
    }

    // ---- epilogue: conv bias + BN + ReLU
    float* Ob = out + (size_t)bz * CC * NPIX;
#pragma unroll
    for (int ms = 0; ms < 4; ++ms) {
        int ma = m0 + wm0 + ms * 16 + g;
        int mb = ma + 8;
        float sca = bg[ma] * rsqrtf(bv[ma] + EPSBN);
        float scb = bg[mb] * rsqrtf(bv[mb] + EPSBN);
        float sha = bb[ma] - bm[ma] * sca + bconv[ma] * sca;
        float shb = bb[mb] - bm[mb] * scb + bconv[mb] * scb;
        float* cpa = Ob + (size_t)ma * NPIX;
        float* cpb = Ob + (size_t)mb * NPIX;
#pragma unroll
        for (int ns = 0; ns < 4; ++ns) {
            int n = p0 + wn0 + ns * 8 + tig * 2;
            cpa[n]     = fmaxf(acc[ms][ns][0] * sca + sha, 0.f);
            cpa[n + 1] = fmaxf(acc[ms][ns][1] * sca + sha, 0.f);
            cpb[n]     = fmaxf(acc[ms][ns][2] * scb + shb, 0.f);
            cpb[n + 1] = fmaxf(acc[ms][ns][3] * scb + shb, 0.f);
        }
    }
}

// ---------------- energy = q^T k, 3xTF32 tensor cores (fp32-grade accuracy) -------
// E[b][i][j] = sum_c q[b][c][i] * k[b][c][j].  A(m,kk)=q[kk*NPIX+m] (m-contig),
// B(n,kk)=k[kk*NPIX+n] (n-contig). K = CR = 64, chunk 16. Same structure as conv.
__global__ void __launch_bounds__(256) energy_3xtf32(
        const float* __restrict__ Q, const float* __restrict__ Km,
        float* __restrict__ E, long long bQK_, long long bAT_)
{
    __shared__ uint32_t As_hi[128 * 16];
    __shared__ uint32_t As_lo[128 * 16];
    __shared__ uint32_t Bs_hi[128 * 16];
    __shared__ uint32_t Bs_lo[128 * 16];

    const int bz = blockIdx.z;
    const float* Qb = Q  + (size_t)bz * bQK_;
    const float* Kb = Km + (size_t)bz * bQK_;
    const int m0 = blockIdx.y * 128, n0 = blockIdx.x * 128;

    const int tid  = threadIdx.x;
    const int wid  = tid >> 5, lane = tid & 31;
    const int g    = lane >> 2, tig = lane & 3;
    const int wm0  = (wid & 1) * 64;
    const int wn0  = (wid >> 1) * 32;

    const int row = tid & 127;   // m (for A) / n (for B)
    const int kb  = tid >> 7;    // 0/1; kk = kb + t*2

    float acc[4][4][4];
#pragma unroll
    for (int i = 0; i < 4; ++i)
#pragma unroll
        for (int j = 0; j < 4; ++j)
#pragma unroll
            for (int c = 0; c < 4; ++c) acc[i][j][c] = 0.f;

    float apre[8], bpre[8];
#pragma unroll
    for (int t = 0; t < 8; ++t) {
        int kk = kb + t * 2;
        apre[t] = Qb[(size_t)kk * NPIX + (m0 + row)];
        bpre[t] = Kb[(size_t)kk * NPIX + (n0 + row)];
    }

    for (int k0 = 0; k0 < CR; k0 += 16) {
#pragma unroll
        for (int t = 0; t < 8; ++t) {
            int kk = kb + t * 2;
            int idx = row * 16 + (kk ^ ((row & 7) << 1));
            float va = apre[t];
            uint32_t ha = f2tf32(va);
            As_hi[idx] = ha;
            As_lo[idx] = f2tf32(va - __uint_as_float(ha));
            float vb = bpre[t];
            uint32_t hb = f2tf32(vb);
            Bs_hi[idx] = hb;
            Bs_lo[idx] = f2tf32(vb - __uint_as_float(hb));
        }
        __syncthreads();

        if (k0 + 16 < CR) {
#pragma unroll
            for (int t = 0; t < 8; ++t) {
                int kk = k0 + 16 + kb + t * 2;
                apre[t] = Qb[(size_t)kk * NPIX + (m0 + row)];
                bpre[t] = Kb[(size_t)kk * NPIX + (n0 + row)];
            }
        }

#pragma unroll
        for (int ks = 0; ks < 2; ++ks) {
            const int kk = ks * 8 + tig;
            const int sw = g << 1;
            uint32_t ah[4][4], al[4][4], bh[4][2], bl[4][2];
#pragma unroll
            for (int ms = 0; ms < 4; ++ms) {
                int mm = wm0 + ms * 16 + g;
                int i0 = mm * 16 + (kk ^ sw);
                int i1 = (mm + 8) * 16 + (kk ^ sw);
                int i2 = mm * 16 + ((kk + 4) ^ sw);
                int i3 = (mm + 8) * 16 + ((kk + 4) ^ sw);
                ah[ms][0] = As_hi[i0]; ah[ms][1] = As_hi[i1];
                ah[ms][2] = As_hi[i2]; ah[ms][3] = As_hi[i3];
                al[ms][0] = As_lo[i0]; al[ms][1] = As_lo[i1];
                al[ms][2] = As_lo[i2]; al[ms][3] = As_lo[i3];
            }
#pragma unroll
            for (int ns = 0; ns < 4; ++ns) {
                int nn = wn0 + ns * 8 + g;
                int i0 = nn * 16 + (kk ^ sw);
                int i1 = nn * 16 + ((kk + 4) ^ sw);
                bh[ns][0] = Bs_hi[i0]; bh[ns][1] = Bs_hi[i1];
                bl[ns][0] = Bs_lo[i0]; bl[ns][1] = Bs_lo[i1];
            }
#pragma unroll
            for (int ms = 0; ms < 4; ++ms)
#pragma unroll
                for (int ns = 0; ns < 4; ++ns) {
                    mma_tf32(acc[ms][ns], ah[ms], bh[ns]);
                    mma_tf32(acc[ms][ns], ah[ms], bl[ns]);
                    mma_tf32(acc[ms][ns], al[ms], bh[ns]);
                }
        }
        __syncthreads();
    }

    float* Cb = E + (size_t)bz * bAT_;
#pragma unroll
    for (int ms = 0; ms < 4; ++ms) {
        int ma = m0 + wm0 + ms * 16 + g;
        int mb = ma + 8;
        float* cpa = Cb + (size_t)ma * NPIX;
        float* cpb = Cb + (size_t)mb * NPIX;
#pragma unroll
        for (int ns = 0; ns < 4; ++ns) {
            int n = n0 + wn0 + ns * 8 + tig * 2;
            cpa[n]     = acc[ms][ns][0];
            cpa[n + 1] = acc[ms][ns][1];
            cpb[n]     = acc[ms][ns][2];
            cpb[n + 1] = acc[ms][ns][3];
        }
    }
}

// ---------------- fp32 tiled SGEMM (q/k projections) ------------------------------
template<int TM, int TN>
__global__ void __launch_bounds__(256) gemmT(
        const float* __restrict__ A, long long batchA, int Am, int Ak,
        const float* __restrict__ B, long long batchB, int Bk, int Bn,
        float* __restrict__ C, long long batchC,
        int M, int N, int K,
        const float* __restrict__ bias,
        const float* __restrict__ resid, long long batchR,
        const float* __restrict__ gamma)
{
    constexpr int RM = TM / 16;
    constexpr int RN = TN / 16;
    __shared__ float As[16][TM];
    __shared__ float Bs[16][TN];

    const int bz = blockIdx.z;
    const float* Ab = A + (size_t)bz * batchA;
    const float* Bb = B + (size_t)bz * batchB;
    const int m0 = blockIdx.y * TM, n0 = blockIdx.x * TN;
    const int tid = threadIdx.x;
    const int tx = tid & 15, ty = tid >> 4;

    float acc[RM][RN];
#pragma unroll
    for (int i = 0; i < RM; ++i)
#pragma unroll
        for (int j = 0; j < RN; ++j) acc[i][j] = 0.f;

    for (int k0 = 0; k0 < K; k0 += 16) {
        if (Ak == 1) {
#pragma unroll
            for (int i = tid; i < TM * 16; i += 256) {
                int kk = i & 15, mm = i >> 4;
                As[kk][mm] = Ab[(size_t)(m0 + mm) * Am + (k0 + kk)];
            }
        } else {
#pragma unroll
            for (int i = tid; i < TM * 16; i += 256) {
                int mm = i % TM, kk = i / TM;
                As[kk][mm] = Ab[(size_t)(m0 + mm) * Am + (size_t)(k0 + kk) * Ak];
            }
        }
        if (Bk == 1) {
#pragma unroll
            for (int i = tid; i < TN * 16; i += 256) {
                int kk = i & 15, nn = i >> 4;
                Bs[kk][nn] = Bb[(size_t)(k0 + kk) + (size_t)(n0 + nn) * Bn];
            }
        } else {
#pragma unroll
            for (int i = tid; i < TN * 16; i += 256) {
                int nn = i % TN, kk = i / TN;
                Bs[kk][nn] = Bb[(size_t)(k0 + kk) * Bk + (size_t)(n0 + nn) * Bn];
            }
        }
        __syncthreads();

#pragma unroll
        for (int kk = 0; kk < 16; ++kk) {
            float a[RM], bv[RN];
#pragma unroll
            for (int i = 0; i < RM; ++i) a[i] = As[kk][ty * RM + i];
#pragma unroll
            for (int j = 0; j < RN; ++j) bv[j] = Bs[kk][tx * RN + j];
#pragma unroll
            for (int i = 0; i < RM; ++i)
#pragma unroll
                for (int j = 0; j < RN; ++j) acc[i][j] += a[i] * bv[j];
        }
        __syncthreads();
    }

    float* Cb = C + (size_t)bz * batchC;
    const float gm = resid ? gamma[0] : 0.f;
#pragma unroll
    for (int i = 0; i < RM; ++i) {
        int m = m0 + ty * RM + i;
        float bi = bias ? bias[m] : 0.f;
        const float* rp = resid ? (resid + (size_t)bz * batchR + (size_t)m * N) : nullptr;
        float* cp = Cb + (size_t)m * N;
#pragma unroll
        for (int j = 0; j < RN; ++j) {
            int n = n0 + tx * RN + j;
            float v = acc[i][j] + bi;
            if (rp) v = gm * v + rp[n];
            cp[n] = v;
        }
    }
}

// ---------------- tf32 tensor-core GEMM (tolerant path: v-proj, attn*V) ----------
__global__ void __launch_bounds__(256) gemm_tf32(
        const float* __restrict__ A, long long batchA, int Am,
        const float* __restrict__ B, long long batchB, int Bk, int Bn,
        float* __restrict__ C, long long batchC,
        int M, int N, int K,
        const float* __restrict__ bias,
        const float* __restrict__ resid, long long batchR,
        const float* __restrict__ gamma)
{
    __shared__ uint32_t As[128 * 32];
    __shared__ uint32_t Bs[128 * 32];

    const int bz  = blockIdx.z;
    const float* Ab = A + (size_t)bz * batchA;
    const float* Bb = B + (size_t)bz * batchB;
    const int m0 = blockIdx.y * 128, n0 = blockIdx.x * 128;
    const int tid  = threadIdx.x;
    const int wid  = tid >> 5, lane = tid & 31;
    const int g    = lane >> 2, tig = lane & 3;
    const int wm0  = (wid & 1) * 64;
    const int wn0  = (wid >> 1) * 32;

    float acc[4][4][4];
#pragma unroll
    for (int i = 0; i < 4; ++i)
#pragma unroll
        for (int j = 0; j < 4; ++j)
#pragma unroll
            for (int c = 0; c < 4; ++c) acc[i][j][c] = 0.f;

    for (int k0 = 0; k0 < K; k0 += 32) {
#pragma unroll
        for (int i = tid; i < 4096; i += 256) {
            int kk = i & 31, mm = i >> 5;
            As[mm * 32 + (kk ^ ((mm & 7) << 2))] =
                f2tf32(Ab[(size_t)(m0 + mm) * Am + (k0 + kk)]);
        }
        if (Bk == 1) {
#pragma unroll
            for (int i = tid; i < 4096; i += 256) {
                int kk = i & 31, nn = i >> 5;
                Bs[nn * 32 + (kk ^ ((nn & 7) << 2))] =
                    f2tf32(Bb[(size_t)(k0 + kk) + (size_t)(n0 + nn) * Bn]);
            }
        } else {
#pragma unroll
            for (int i = tid; i < 4096; i += 256) {
                int nn = i & 127, kk = i >> 7;
                Bs[nn * 32 + (kk ^ ((nn & 7) << 2))] =
                    f2tf32(Bb[(size_t)(k0 + kk) * Bk + (n0 + nn)]);
            }
        }
        __syncthreads();

#pragma unroll
        for (int ks = 0; ks < 4; ++ks) {
            const int kk = ks * 8 + tig;
            uint32_t af[4][4], bf[4][2];
#pragma unroll
            for (int ms = 0; ms < 4; ++ms) {
                int mm = wm0 + ms * 16 + g;
                int sw = g << 2;
                af[ms][0] = As[mm * 32 + (kk ^ sw)];
                af[ms][1] = As[(mm + 8) * 32 + (kk ^ sw)];
                af[ms][2] = As[mm * 32 + ((kk + 4) ^ sw)];
                af[ms][3] = As[(mm + 8) * 32 + ((kk + 4) ^ sw)];
            }
#pragma unroll
            for (int ns = 0; ns < 4; ++ns) {
                int nn = wn0 + ns * 8 + g;
                int sw = g << 2;
                bf[ns][0] = Bs[nn * 32 + (kk ^ sw)];
                bf[ns][1] = Bs[nn * 32 + ((kk + 4) ^ sw)];
            }
#pragma unroll
            for (int ms = 0; ms < 4; ++ms)
#pragma unroll
                for (int ns = 0; ns < 4; ++ns)
                    mma_tf32(acc[ms][ns], af[ms], bf[ns]);
        }
        __syncthreads();
    }

    float* Cb = C + (size_t)bz * batchC;
    const float gm = resid ? gamma[0] : 0.f;
#pragma unroll
    for (int ms = 0; ms < 4; ++ms) {
        int ma = m0 + wm0 + ms * 16 + g;
        int mb = ma + 8;
        float bia = bias ? bias[ma] : 0.f;
        float bib = bias ? bias[mb] : 0.f;
        float* cpa = Cb + (size_t)ma * N;
        float* cpb = Cb + (size_t)mb * N;
        const float* rpa = resid ? (resid + (size_t)bz * batchR + (size_t)ma * N) : nullptr;
        const float* rpb = resid ? (resid + (size_t)bz * batchR + (size_t)mb * N) : nullptr;
#pragma unroll
        for (int ns = 0; ns < 4; ++ns) {
            int n = n0 + wn0 + ns * 8 + tig * 2;
            float v0 = acc[ms][ns][0] + bia;
            float v1 = acc[ms][ns][1] + bia;
            float v2 = acc[ms][ns][2] + bib;
            float v3 = acc[ms][ns][3] + bib;
            if (resid) {
                v0 = gm * v0 + rpa[n];
                v1 = gm * v1 + rpa[n + 1];
                v2 = gm * v2 + rpb[n];
                v3 = gm * v3 + rpb[n + 1];
            }
            cpa[n]     = v0;
            cpa[n + 1] = v1;
            cpb[n]     = v2;
            cpb[n + 1] = v3;
        }
    }
}

// ---------------- row softmax over 2304 columns ----------------------------------
__global__ void softmax_rows(float* __restrict__ attn)
{
    __shared__ float red[8];
    const size_t row = blockIdx.x;
    float* p = attn + row * (size_t)NPIX;
    const int tid = threadIdx.x;
    const int lane = tid & 31, wid = tid >> 5;

    float v[9];
    float mx = -3.4e38f;
#pragma unroll
    for (int i = 0; i < 9; ++i) {
        v[i] = p[tid + i * 256];
        mx = fmaxf(mx, v[i]);
    }
#pragma unroll
    for (int o = 16; o > 0; o >>= 1) mx = fmaxf(mx, __shfl_xor_sync(0xffffffffu, mx, o));
    if (lane == 0) red[wid] = mx;
    __syncthreads();
    mx = red[0];
#pragma unroll
    for (int i = 1; i < 8; ++i) mx = fmaxf(mx, red[i]);
    __syncthreads();

    float s = 0.f;
#pragma unroll
    for (int i = 0; i < 9; ++i) {
        v[i] = __expf(v[i] - mx);
        s += v[i];
    }
#pragma unroll
    for (int o = 16; o > 0; o >>= 1) s += __shfl_xor_sync(0xffffffffu, s, o);
    if (lane == 0) red[wid] = s;
    __syncthreads();
    s = 0.f;
#pragma unroll
    for (int i = 0; i < 8; ++i) s += red[i];
    const float inv = 1.f / s;
#pragma unroll
    for (int i = 0; i < 9; ++i) p[tid + i * 256] = v[i] * inv;
}

// ---------------- launcher -------------------------------------------------------
extern "C" void kernel_launch(void* const* d_in, const int* in_sizes, int n_in,
                              void* d_out, int out_size)
{
    const float* x     = (const float*)d_in[0];
    const float* w_pre = (const float*)d_in[1];
    const float* b_pre = (const float*)d_in[2];
    const float* bn1g  = (const float*)d_in[3];
    const float* bn1b  = (const float*)d_in[4];
    const float* bn1m  = (const float*)d_in[5];
    const float* bn1v  = (const float*)d_in[6];
    const float* w_q   = (const float*)d_in[7];
    const float* b_q   = (const float*)d_in[8];
    const float* w_k   = (const float*)d_in[9];
    const float* b_k   = (const float*)d_in[10];
    const float* w_v   = (const float*)d_in[11];
    const float* b_v   = (const float*)d_in[12];
    const float* w_f   = (const float*)d_in[13];
    const float* b_f   = (const float*)d_in[14];
    const float* bn2g  = (const float*)d_in[15];
    const float* bn2b  = (const float*)d_in[16];
    const float* bn2m  = (const float*)d_in[17];
    const float* bn2v  = (const float*)d_in[18];
    const float* gamma = (const float*)d_in[19];
    float* out = (float*)d_out;

    float *x1, *q, *k, *v, *of, *attn;
    cudaGetSymbolAddress((void**)&x1,   g_x1);
    cudaGetSymbolAddress((void**)&q,    g_q);
    cudaGetSymbolAddress((void**)&k,    g_k);
    cudaGetSymbolAddress((void**)&v,    g_v);
    cudaGetSymbolAddress((void**)&of,   g_of);
    cudaGetSymbolAddress((void**)&attn, g_attn);

    const long long bX1 = (long long)CC * NPIX;
    const long long bQK = (long long)CR * NPIX;
    const long long bAT = (long long)NPIX * NPIX;

    // 1) conv1 + BN + ReLU -> x1  (3xTF32 tensor cores, prefetch-pipelined)
    conv3x3_tc<<<dim3(NPIX / 128, 2, BB), 256>>>(
        x, w_pre, b_pre, bn1g, bn1b, bn1m, bn1v, x1, CIN1);

    // 2) q/k projections: fp32 (feed the softmax-sensitive energy path)
    gemmT<64, 128><<<dim3(NPIX / 128, CR / 64, BB), 256>>>(
        w_q, 0, CC, 1, x1, bX1, NPIX, 1, q, bQK, CR, NPIX, CC, b_q, nullptr, 0, nullptr);
    gemmT<64, 128><<<dim3(NPIX / 128, CR / 64, BB), 256>>>(
        w_k, 0, CC, 1, x1, bX1, NPIX, 1, k, bQK, CR, NPIX, CC, b_k, nullptr, 0, nullptr);
    // v projection: tf32 tensor cores (tolerant path)
    gemm_tf32<<<dim3(NPIX / 128, CC / 128, BB), 256>>>(
        w_v, 0, CC, x1, bX1, NPIX, 1, v, bX1, CC, NPIX, CC, b_v, nullptr, 0, nullptr);

    // 3-5) attention in chunks of CHUNK batches
    for (int c0 = 0; c0 < BB; c0 += CHUNK) {
        const float* qb = q  + (size_t)c0 * bQK;
        const float* kb = k  + (size_t)c0 * bQK;
        const float* vb = v  + (size_t)c0 * bX1;
        const float* xb = x1 + (size_t)c0 * bX1;
        float*       ob = of + (size_t)c0 * bX1;

        // energy: 3xTF32 tensor cores (fp32-grade accuracy for the softmax path)
        energy_3xtf32<<<dim3(NPIX / 128, NPIX / 128, CHUNK), 256>>>(
            qb, kb, attn, bQK, bAT);

        softmax_rows<<<CHUNK * NPIX, 256>>>(attn);

        // attn*V + residual: tf32 tensor cores
        gemm_tf32<<<dim3(NPIX / 128, CC / 128, CHUNK), 256>>>(
            vb, bX1, NPIX, attn, bAT, 1, NPIX,
            ob, bX1, CC, NPIX, NPIX, nullptr, xb, bX1, gamma);
    }

    // 6) conv2 + BN + ReLU -> d_out (3xTF32 tensor cores, prefetch-pipelined)
    conv3x3_tc<<<dim3(NPIX / 128, 2, BB), 256>>>(
        of, w_f, b_f, bn2g, bn2b, bn2m, bn2v, out, CC);
}

// round 12
// speedup vs baseline: 4.1197x; 1.1228x over previous
#include <cuda_runtime.h>
#include <math.h>
#include <stdint.h>

// Problem constants
#define BB    8
#define CIN1  512
#define CC    256
#define HH    48
#define WW    48
#define NPIX  2304      // 48*48
#define CR    64        // C/r
#define EPSBN 1e-5f
#define CHUNK 4         // attention batches processed per chunk

// ---------------- scratch (static device globals; ~151 MB total) ----------------
__device__ float g_x1  [(size_t)BB * CC * NPIX];
__device__ float g_q   [(size_t)BB * CR * NPIX];
__device__ float g_k   [(size_t)BB * CR * NPIX];
__device__ float g_v   [(size_t)BB * CC * NPIX];
__device__ float g_of  [(size_t)BB * CC * NPIX];
__device__ float g_attn[(size_t)CHUNK * NPIX * NPIX];

// ---------------- tf32 helpers ----------------------------------------------------
__device__ __forceinline__ uint32_t f2tf32(float f) {
    uint32_t r;
    asm("cvt.rna.tf32.f32 %0, %1;" : "=r"(r) : "f"(f));
    return r;
}
__device__ __forceinline__ void mma_tf32(float* d, const uint32_t* a, const uint32_t* b) {
    asm volatile(
        "mma.sync.aligned.m16n8k8.row.col.f32.tf32.tf32.f32 "
        "{%0,%1,%2,%3}, {%4,%5,%6,%7}, {%8,%9}, {%0,%1,%2,%3};"
        : "+f"(d[0]), "+f"(d[1]), "+f"(d[2]), "+f"(d[3])
        : "r"(a[0]), "r"(a[1]), "r"(a[2]), "r"(a[3]), "r"(b[0]), "r"(b[1]));
}

// ---------------- conv3x3 (pad=1) + BN + ReLU as implicit GEMM, 3xTF32 ------------
// Register-prefetch double-buffered.
__global__ void __launch_bounds__(256) conv3x3_tc(
        const float* __restrict__ X,
        const float* __restrict__ W,
        const float* __restrict__ bconv,
        const float* __restrict__ bg,
        const float* __restrict__ bb,
        const float* __restrict__ bm,
        const float* __restrict__ bv,
        float* __restrict__ out,
        int CIN)
{
    __shared__ uint32_t As_hi[128 * 16];
    __shared__ uint32_t As_lo[128 * 16];
    __shared__ uint32_t Bs_hi[128 * 16];
    __shared__ uint32_t Bs_lo[128 * 16];

    const int bz = blockIdx.z;
    const int K9 = CIN * 9;
    const float* Xb = X + (size_t)bz * CIN * NPIX;
    const int m0 = blockIdx.y * 128, p0 = blockIdx.x * 128;

    const int tid  = threadIdx.x;
    const int wid  = tid >> 5, lane = tid & 31;
    const int g    = lane >> 2, tig = lane & 3;
    const int wm0  = (wid & 1) * 64;
    const int wn0  = (wid >> 1) * 32;

    const int a_kk = tid & 15;
    const int a_m  = tid >> 4;
    const int b_nn = tid & 127;
    const int b_k  = tid >> 7;
    const int p    = p0 + b_nn;
    const int prow = p / 48;
    const int pcol = p - prow * 48;

    float acc[4][4][4];
#pragma unroll
    for (int i = 0; i < 4; ++i)
#pragma unroll
        for (int j = 0; j < 4; ++j)
#pragma unroll
            for (int c = 0; c < 4; ++c) acc[i][j][c] = 0.f;

    float apre[8], bpre[8];
#pragma unroll
    for (int t = 0; t < 8; ++t)
        apre[t] = W[(size_t)(m0 + a_m + t * 16) * K9 + a_kk];
#pragma unroll
    for (int t = 0; t < 8; ++t) {
        int k   = b_k + t * 2;
        int cin = k / 9;
        int tap = k - cin * 9;
        int t3  = tap / 3;
        int rr  = prow + t3 - 1;
        int cc  = pcol + (tap - t3 * 3) - 1;
        float v = 0.f;
        if ((unsigned)rr < 48u && (unsigned)cc < 48u)
            v = Xb[(size_t)cin * NPIX + rr * 48 + cc];
        bpre[t] = v;
    }

    for (int k0 = 0; k0 < K9; k0 += 16) {
#pragma unroll
        for (int t = 0; t < 8; ++t) {
            int mm  = a_m + t * 16;
            float v = apre[t];
            uint32_t hi = f2tf32(v);
            int idx = mm * 16 + (a_kk ^ ((mm & 7) << 1));
            As_hi[idx] = hi;
            As_lo[idx] = f2tf32(v - __uint_as_float(hi));
        }
#pragma unroll
        for (int t = 0; t < 8; ++t) {
            int kk  = b_k + t * 2;
            float v = bpre[t];
            uint32_t hi = f2tf32(v);
            int idx = b_nn * 16 + (kk ^ ((b_nn & 7) << 1));
            Bs_hi[idx] = hi;
            Bs_lo[idx] = f2tf32(v - __uint_as_float(hi));
        }
        __syncthreads();

        if (k0 + 16 < K9) {
#pragma unroll
            for (int t = 0; t < 8; ++t)
                apre[t] = W[(size_t)(m0 + a_m + t * 16) * K9 + (k0 + 16 + a_kk)];
#pragma unroll
            for (int t = 0; t < 8; ++t) {
                int k   = k0 + 16 + b_k + t * 2;
                int cin = k / 9;
                int tap = k - cin * 9;
                int t3  = tap / 3;
                int rr  = prow + t3 - 1;
                int cc  = pcol + (tap - t3 * 3) - 1;
                float v = 0.f;
                if ((unsigned)rr < 48u && (unsigned)cc < 48u)
                    v = Xb[(size_t)cin * NPIX + rr * 48 + cc];
                bpre[t] = v;
            }
        }

#pragma unroll
        for (int ks = 0; ks < 2; ++ks) {
            const int kk = ks * 8 + tig;
            const int sw = g << 1;
            uint32_t ah[4][4], al[4][4], bh[4][2], bl[4][2];
#pragma unroll
            for (int ms = 0; ms < 4; ++ms) {
                int mm = wm0 + ms * 16 + g;
                int i0 = mm * 16 + (kk ^ sw);
                int i1 = (mm + 8) * 16 + (kk ^ sw);
                int i2 = mm * 16 + ((kk + 4) ^ sw);
                int i3 = (mm + 8) * 16 + ((kk + 4) ^ sw);
                ah[ms][0] = As_hi[i0]; ah[ms][1] = As_hi[i1];
                ah[ms][2] = As_hi[i2]; ah[ms][3] = As_hi[i3];
                al[ms][0] = As_lo[i0]; al[ms][1] = As_lo[i1];
                al[ms][2] = As_lo[i2]; al[ms][3] = As_lo[i3];
            }
#pragma unroll
            for (int ns = 0; ns < 4; ++ns) {
                int nn = wn0 + ns * 8 + g;
                int i0 = nn * 16 + (kk ^ sw);
                int i1 = nn * 16 + ((kk + 4) ^ sw);
                bh[ns][0] = Bs_hi[i0]; bh[ns][1] = Bs_hi[i1];
                bl[ns][0] = Bs_lo[i0]; bl[ns][1] = Bs_lo[i1];
            }
#pragma unroll
            for (int ms = 0; ms < 4; ++ms)
#pragma unroll
                for (int ns = 0; ns < 4; ++ns) {
                    mma_tf32(acc[ms][ns], ah[ms], bh[ns]);
                    mma_tf32(acc[ms][ns], ah[ms], bl[ns]);
                    mma_tf32(acc[ms][ns], al[ms], bh[ns]);
                }
        }
        __syncthreads();
    }

    float* Ob = out + (size_t)bz * CC * NPIX;
#pragma unroll
    for (int ms = 0; ms < 4; ++ms) {
        int ma = m0 + wm0 + ms * 16 + g;
        int mb = ma + 8;
        float sca = bg[ma] * rsqrtf(bv[ma] + EPSBN);
        float scb = bg[mb] * rsqrtf(bv[mb] + EPSBN);
        float sha = bb[ma] - bm[ma] * sca + bconv[ma] * sca;
        float shb = bb[mb] - bm[mb] * scb + bconv[mb] * scb;
        float* cpa = Ob + (size_t)ma * NPIX;
        float* cpb = Ob + (size_t)mb * NPIX;
#pragma unroll
        for (int ns = 0; ns < 4; ++ns) {
            int n = p0 + wn0 + ns * 8 + tig * 2;
            cpa[n]     = fmaxf(acc[ms][ns][0] * sca + sha, 0.f);
            cpa[n + 1] = fmaxf(acc[ms][ns][1] * sca + sha, 0.f);
            cpb[n]     = fmaxf(acc[ms][ns][2] * scb + shb, 0.f);
            cpb[n + 1] = fmaxf(acc[ms][ns][3] * scb + shb, 0.f);
        }
    }
}

// ---------------- fused q/k projection, 3xTF32 (fp32-grade) -----------------------
// M=128 tile: rows 0-63 = Wq rows, 64-127 = Wk rows. B = x1 (n-contig). K = CC.
__global__ void __launch_bounds__(256) qk_proj_3x(
        const float* __restrict__ Wq, const float* __restrict__ Wk,
        const float* __restrict__ bq, const float* __restrict__ bk,
        const float* __restrict__ X1, long long bX1_,
        float* __restrict__ Qo, float* __restrict__ Ko, long long bQK_)
{
    __shared__ uint32_t As_hi[128 * 16];
    __shared__ uint32_t As_lo[128 * 16];
    __shared__ uint32_t Bs_hi[128 * 16];
    __shared__ uint32_t Bs_lo[128 * 16];

    const int bz = blockIdx.z;
    const float* Xb = X1 + (size_t)bz * bX1_;
    const int n0 = blockIdx.x * 128;

    const int tid  = threadIdx.x;
    const int wid  = tid >> 5, lane = tid & 31;
    const int g    = lane >> 2, tig = lane & 3;
    const int wm0  = (wid & 1) * 64;
    const int wn0  = (wid >> 1) * 32;

    const int a_kk = tid & 15;
    const int a_m  = tid >> 4;          // row base; row = a_m + t*16 (t<4: Wq, t>=4: Wk)
    const int b_nn = tid & 127;
    const int b_k  = tid >> 7;

    float acc[4][4][4];
#pragma unroll
    for (int i = 0; i < 4; ++i)
#pragma unroll
        for (int j = 0; j < 4; ++j)
#pragma unroll
            for (int c = 0; c < 4; ++c) acc[i][j][c] = 0.f;

    float apre[8], bpre[8];
#pragma unroll
    for (int t = 0; t < 4; ++t) {
        apre[t]     = Wq[(size_t)(a_m + t * 16) * CC + a_kk];
        apre[t + 4] = Wk[(size_t)(a_m + t * 16) * CC + a_kk];
    }
#pragma unroll
    for (int t = 0; t < 8; ++t)
        bpre[t] = Xb[(size_t)(b_k + t * 2) * NPIX + (n0 + b_nn)];

    for (int k0 = 0; k0 < CC; k0 += 16) {
#pragma unroll
        for (int t = 0; t < 8; ++t) {
            int mm  = a_m + ((t & 3) * 16) + ((t >> 2) * 64);
            float v = apre[t];
            uint32_t hi = f2tf32(v);
            int idx = mm * 16 + (a_kk ^ ((mm & 7) << 1));
            As_hi[idx] = hi;
            As_lo[idx] = f2tf32(v - __uint_as_float(hi));
        }
#pragma unroll
        for (int t = 0; t < 8; ++t) {
            int kk  = b_k + t * 2;
            float v = bpre[t];
            uint32_t hi = f2tf32(v);
            int idx = b_nn * 16 + (kk ^ ((b_nn & 7) << 1));
            Bs_hi[idx] = hi;
            Bs_lo[idx] = f2tf32(v - __uint_as_float(hi));
        }
        __syncthreads();

        if (k0 + 16 < CC) {
#pragma unroll
            for (int t = 0; t < 4; ++t) {
                apre[t]     = Wq[(size_t)(a_m + t * 16) * CC + (k0 + 16 + a_kk)];
                apre[t + 4] = Wk[(size_t)(a_m + t * 16) * CC + (k0 + 16 + a_kk)];
            }
#pragma unroll
            for (int t = 0; t < 8; ++t)
                bpre[t] = Xb[(size_t)(k0 + 16 + b_k + t * 2) * NPIX + (n0 + b_nn)];
        }

#pragma unroll
        for (int ks = 0; ks < 2; ++ks) {
            const int kk = ks * 8 + tig;
            const int sw = g << 1;
            uint32_t ah[4][4], al[4][4], bh[4][2], bl[4][2];
#pragma unroll
            for (int ms = 0; ms < 4; ++ms) {
                int mm = wm0 + ms * 16 + g;
                int i0 = mm * 16 + (kk ^ sw);
                int i1 = (mm + 8) * 16 + (kk ^ sw);
                int i2 = mm * 16 + ((kk + 4) ^ sw);
                int i3 = (mm + 8) * 16 + ((kk + 4) ^ sw);
                ah[ms][0] = As_hi[i0]; ah[ms][1] = As_hi[i1];
                ah[ms][2] = As_hi[i2]; ah[ms][3] = As_hi[i3];
                al[ms][0] = As_lo[i0]; al[ms][1] = As_lo[i1];
                al[ms][2] = As_lo[i2]; al[ms][3] = As_lo[i3];
            }
#pragma unroll
            for (int ns = 0; ns < 4; ++ns) {
                int nn = wn0 + ns * 8 + g;
                int i0 = nn * 16 + (kk ^ sw);
                int i1 = nn * 16 + ((kk + 4) ^ sw);
                bh[ns][0] = Bs_hi[i0]; bh[ns][1] = Bs_hi[i1];
                bl[ns][0] = Bs_lo[i0]; bl[ns][1] = Bs_lo[i1];
            }
#pragma unroll
            for (int ms = 0; ms < 4; ++ms)
#pragma unroll
                for (int ns = 0; ns < 4; ++ns) {
                    mma_tf32(acc[ms][ns], ah[ms], bh[ns]);
                    mma_tf32(acc[ms][ns], ah[ms], bl[ns]);
                    mma_tf32(acc[ms][ns], al[ms], bh[ns]);
                }
        }
        __syncthreads();
    }

    // epilogue: rows <64 -> Q, >=64 -> K (static per wm0)
#pragma unroll
    for (int ms = 0; ms < 4; ++ms) {
        int ma = wm0 + ms * 16 + g;     // 0..127
        int mb = ma + 8;
        int ra = (ma < 64) ? ma : ma - 64;
        int rb = (mb < 64) ? mb : mb - 64;
        float bia = (ma < 64) ? bq[ra] : bk[ra];
        float bib = (mb < 64) ? bq[rb] : bk[rb];
        float* cpa = ((ma < 64) ? Qo : Ko) + (size_t)bz * bQK_ + (size_t)ra * NPIX;
        float* cpb = ((mb < 64) ? Qo : Ko) + (size_t)bz * bQK_ + (size_t)rb * NPIX;
#pragma unroll
        for (int ns = 0; ns < 4; ++ns) {
            int n = n0 + wn0 + ns * 8 + tig * 2;
            cpa[n]     = acc[ms][ns][0] + bia;
            cpa[n + 1] = acc[ms][ns][1] + bia;
            cpb[n]     = acc[ms][ns][2] + bib;
            cpb[n + 1] = acc[ms][ns][3] + bib;
        }
    }
}

// ---------------- energy = q^T k, 3xTF32 (fp32-grade) -----------------------------
__global__ void __launch_bounds__(256) energy_3xtf32(
        const float* __restrict__ Q, const float* __restrict__ Km,
        float* __restrict__ E, long long bQK_, long long bAT_)
{
    __shared__ uint32_t As_hi[128 * 16];
    __shared__ uint32_t As_lo[128 * 16];
    __shared__ uint32_t Bs_hi[128 * 16];
    __shared__ uint32_t Bs_lo[128 * 16];

    const int bz = blockIdx.z;
    const float* Qb = Q  + (size_t)bz * bQK_;
    const float* Kb = Km + (size_t)bz * bQK_;
    const int m0 = blockIdx.y * 128, n0 = blockIdx.x * 128;

    const int tid  = threadIdx.x;
    const int wid  = tid >> 5, lane = tid & 31;
    const int g    = lane >> 2, tig = lane & 3;
    const int wm0  = (wid & 1) * 64;
    const int wn0  = (wid >> 1) * 32;

    const int row = tid & 127;
    const int kb  = tid >> 7;

    float acc[4][4][4];
#pragma unroll
    for (int i = 0; i < 4; ++i)
#pragma unroll
        for (int j = 0; j < 4; ++j)
#pragma unroll
            for (int c = 0; c < 4; ++c) acc[i][j][c] = 0.f;

    float apre[8], bpre[8];
#pragma unroll
    for (int t = 0; t < 8; ++t) {
        int kk = kb + t * 2;
        apre[t] = Qb[(size_t)kk * NPIX + (m0 + row)];
        bpre[t] = Kb[(size_t)kk * NPIX + (n0 + row)];
    }

    for (int k0 = 0; k0 < CR; k0 += 16) {
#pragma unroll
        for (int t = 0; t < 8; ++t) {
            int kk = kb + t * 2;
            int idx = row * 16 + (kk ^ ((row & 7) << 1));
            float va = apre[t];
            uint32_t ha = f2tf32(va);
            As_hi[idx] = ha;
            As_lo[idx] = f2tf32(va - __uint_as_float(ha));
            float vb = bpre[t];
            uint32_t hb = f2tf32(vb);
            Bs_hi[idx] = hb;
            Bs_lo[idx] = f2tf32(vb - __uint_as_float(hb));
        }
        __syncthreads();

        if (k0 + 16 < CR) {
#pragma unroll
            for (int t = 0; t < 8; ++t) {
                int kk = k0 + 16 + kb + t * 2;
                apre[t] = Qb[(size_t)kk * NPIX + (m0 + row)];
                bpre[t] = Kb[(size_t)kk * NPIX + (n0 + row)];
            }
        }

#pragma unroll
        for (int ks = 0; ks < 2; ++ks) {
            const int kk = ks * 8 + tig;
            const int sw = g << 1;
            uint32_t ah[4][4], al[4][4], bh[4][2], bl[4][2];
#pragma unroll
            for (int ms = 0; ms < 4; ++ms) {
                int mm = wm0 + ms * 16 + g;
                int i0 = mm * 16 + (kk ^ sw);
                int i1 = (mm + 8) * 16 + (kk ^ sw);
                int i2 = mm * 16 + ((kk + 4) ^ sw);
                int i3 = (mm + 8) * 16 + ((kk + 4) ^ sw);
                ah[ms][0] = As_hi[i0]; ah[ms][1] = As_hi[i1];
                ah[ms][2] = As_hi[i2]; ah[ms][3] = As_hi[i3];
                al[ms][0] = As_lo[i0]; al[ms][1] = As_lo[i1];
                al[ms][2] = As_lo[i2]; al[ms][3] = As_lo[i3];
            }
#pragma unroll
            for (int ns = 0; ns < 4; ++ns) {
                int nn = wn0 + ns * 8 + g;
                int i0 = nn * 16 + (kk ^ sw);
                int i1 = nn * 16 + ((kk + 4) ^ sw);
                bh[ns][0] = Bs_hi[i0]; bh[ns][1] = Bs_hi[i1];
                bl[ns][0] = Bs_lo[i0]; bl[ns][1] = Bs_lo[i1];
            }
#pragma unroll
            for (int ms = 0; ms < 4; ++ms)
#pragma unroll
                for (int ns = 0; ns < 4; ++ns) {
                    mma_tf32(acc[ms][ns], ah[ms], bh[ns]);
                    mma_tf32(acc[ms][ns], ah[ms], bl[ns]);
                    mma_tf32(acc[ms][ns], al[ms], bh[ns]);
                }
        }
        __syncthreads();
    }

    float* Cb = E + (size_t)bz * bAT_;
#pragma unroll
    for (int ms = 0; ms < 4; ++ms) {
        int ma = m0 + wm0 + ms * 16 + g;
        int mb = ma + 8;
        float* cpa = Cb + (size_t)ma * NPIX;
        float* cpb = Cb + (size_t)mb * NPIX;
#pragma unroll
        for (int ns = 0; ns < 4; ++ns) {
            int n = n0 + wn0 + ns * 8 + tig * 2;
            cpa[n]     = acc[ms][ns][0];
            cpa[n + 1] = acc[ms][ns][1];
            cpb[n]     = acc[ms][ns][2];
            cpb[n + 1] = acc[ms][ns][3];
        }
    }
}

// ---------------- 1x tf32 GEMM, K-chunk 16, prefetch-pipelined --------------------
// C[b][m][n] = sum_k A(m,k)*B(k,n) (+bias[m]) (+resid: C = gamma*C + resid)
// A k-contig: A[b*batchA + m*Am + k].
// B: Bk==1 -> k-contig (B[b*batchB + k + n*Bn]); else n-contig (B[b*batchB + k*Bk + n])
__global__ void __launch_bounds__(256) gemm16_tf32(
        const float* __restrict__ A, long long batchA, int Am,
        const float* __restrict__ B, long long batchB, int Bk, int Bn,
        float* __restrict__ C, long long batchC,
        int M, int N, int K,
        const float* __restrict__ bias,
        const float* __restrict__ resid, long long batchR,
        const float* __restrict__ gamma)
{
    __shared__ uint32_t As[128 * 16];
    __shared__ uint32_t Bs[128 * 16];

    const int bz  = blockIdx.z;
    const float* Ab = A + (size_t)bz * batchA;
    const float* Bb = B + (size_t)bz * batchB;
    const int m0 = blockIdx.y * 128, n0 = blockIdx.x * 128;
    const int tid  = threadIdx.x;
    const int wid  = tid >> 5, lane = tid & 31;
    const int g    = lane >> 2, tig = lane & 3;
    const int wm0  = (wid & 1) * 64;
    const int wn0  = (wid >> 1) * 32;

    const int a_kk = tid & 15;
    const int a_m  = tid >> 4;
    const int b_nn = tid & 127;
    const int b_k  = tid >> 7;

    float acc[4][4][4];
#pragma unroll
    for (int i = 0; i < 4; ++i)
#pragma unroll
        for (int j = 0; j < 4; ++j)
#pragma unroll
            for (int c = 0; c < 4; ++c) acc[i][j][c] = 0.f;

    float apre[8], bpre[8];
#pragma unroll
    for (int t = 0; t < 8; ++t)
        apre[t] = Ab[(size_t)(m0 + a_m + t * 16) * Am + a_kk];
    if (Bk == 1) {
#pragma unroll
        for (int t = 0; t < 8; ++t)
            bpre[t] = Bb[a_kk + (size_t)(n0 + a_m + t * 16) * Bn];
    } else {
#pragma unroll
        for (int t = 0; t < 8; ++t)
            bpre[t] = Bb[(size_t)(b_k + t * 2) * Bk + (n0 + b_nn)];
    }

    for (int k0 = 0; k0 < K; k0 += 16) {
#pragma unroll
        for (int t = 0; t < 8; ++t) {
            int mm = a_m + t * 16;
            As[mm * 16 + (a_kk ^ ((mm & 7) << 1))] = f2tf32(apre[t]);
        }
        if (Bk == 1) {
#pragma unroll
            for (int t = 0; t < 8; ++t) {
                int nn = a_m + t * 16;
                Bs[nn * 16 + (a_kk ^ ((nn & 7) << 1))] = f2tf32(bpre[t]);
            }
        } else {
#pragma unroll
            for (int t = 0; t < 8; ++t) {
                int kk = b_k + t * 2;
                Bs[b_nn * 16 + (kk ^ ((b_nn & 7) << 1))] = f2tf32(bpre[t]);
            }
        }
        __syncthreads();

        if (k0 + 16 < K) {
#pragma unroll
            for (int t = 0; t < 8; ++t)
                apre[t] = Ab[(size_t)(m0 + a_m + t * 16) * Am + (k0 + 16 + a_kk)];
            if (Bk == 1) {
#pragma unroll
                for (int t = 0; t < 8; ++t)
                    bpre[t] = Bb[(size_t)(k0 + 16 + a_kk) + (size_t)(n0 + a_m + t * 16) * Bn];
            } else {
#pragma unroll
                for (int t = 0; t < 8; ++t)
                    bpre[t] = Bb[(size_t)(k0 + 16 + b_k + t * 2) * Bk + (n0 + b_nn)];
            }
        }

#pragma unroll
        for (int ks = 0; ks < 2; ++ks) {
            const int kk = ks * 8 + tig;
            const int sw = g << 1;
            uint32_t af[4][4], bf[4][2];
#pragma unroll
            for (int ms = 0; ms < 4; ++ms) {
                int mm = wm0 + ms * 16 + g;
                af[ms][0] = As[mm * 16 + (kk ^ sw)];
                af[ms][1] = As[(mm + 8) * 16 + (kk ^ sw)];
                af[ms][2] = As[mm * 16 + ((kk + 4) ^ sw)];
                af[ms][3] = As[(mm + 8) * 16 + ((kk + 4) ^ sw)];
            }
#pragma unroll
            for (int ns = 0; ns < 4; ++ns) {
                int nn = wn0 + ns * 8 + g;
                bf[ns][0] = Bs[nn * 16 + (kk ^ sw)];
                bf[ns][1] = Bs[nn * 16 + ((kk + 4) ^ sw)];
            }
#pragma unroll
            for (int ms = 0; ms < 4; ++ms)
#pragma unroll
                for (int ns = 0; ns < 4; ++ns)
                    mma_tf32(acc[ms][ns], af[ms], bf[ns]);
        }
        __syncthreads();
    }

    float* Cb = C + (size_t)bz * batchC;
    const float gm = resid ? gamma[0] : 0.f;
#pragma unroll
    for (int ms = 0; ms < 4; ++ms) {
        int ma = m0 + wm0 + ms * 16 + g;
        int mb = ma + 8;
        float bia = bias ? bias[ma] : 0.f;
        float bib = bias ? bias[mb] : 0.f;
        float* cpa = Cb + (size_t)ma * N;
        float* cpb = Cb + (size_t)mb * N;
        const float* rpa = resid ? (resid + (size_t)bz * batchR + (size_t)ma * N) : nullptr;
        const float* rpb = resid ? (resid + (size_t)bz * batchR + (size_t)mb * N) : nullptr;
#pragma unroll
        for (int ns = 0; ns < 4; ++ns) {
            int n = n0 + wn0 + ns * 8 + tig * 2;
            float v0 = acc[ms][ns][0] + bia;
            float v1 = acc[ms][ns][1] + bia;
            float v2 = acc[ms][ns][2] + bib;
            float v3 = acc[ms][ns][3] + bib;
            if (resid) {
                v0 = gm * v0 + rpa[n];
                v1 = gm * v1 + rpa[n + 1];
                v2 = gm * v2 + rpb[n];
                v3 = gm * v3 + rpb[n + 1];
            }
            cpa[n]     = v0;
            cpa[n + 1] = v1;
            cpb[n]     = v2;
            cpb[n + 1] = v3;
        }
    }
}

// ---------------- row softmax over 2304 columns ----------------------------------
__global__ void softmax_rows(float* __restrict__ attn)
{
    __shared__ float red[8];
    const size_t row = blockIdx.x;
    float* p = attn + row * (size_t)NPIX;
    const int tid = threadIdx.x;
    const int lane = tid & 31, wid = tid >> 5;

    float v[9];
    float mx = -3.4e38f;
#pragma unroll
    for (int i = 0; i < 9; ++i) {
        v[i] = p[tid + i * 256];
        mx = fmaxf(mx, v[i]);
    }
#pragma unroll
    for (int o = 16; o > 0; o >>= 1) mx = fmaxf(mx, __shfl_xor_sync(0xffffffffu, mx, o));
    if (lane == 0) red[wid] = mx;
    __syncthreads();
    mx = red[0];
#pragma unroll
    for (int i = 1; i < 8; ++i) mx = fmaxf(mx, red[i]);
    __syncthreads();

    float s = 0.f;
#pragma unroll
    for (int i = 0; i < 9; ++i) {
        v[i] = __expf(v[i] - mx);
        s += v[i];
    }
#pragma unroll
    for (int o = 16; o > 0; o >>= 1) s += __shfl_xor_sync(0xffffffffu, s, o);
    if (lane == 0) red[wid] = s;
    __syncthreads();
    s = 0.f;
#pragma unroll
    for (int i = 0; i < 8; ++i) s += red[i];
    const float inv = 1.f / s;
#pragma unroll
    for (int i = 0; i < 9; ++i) p[tid + i * 256] = v[i] * inv;
}

// ---------------- launcher -------------------------------------------------------
extern "C" void kernel_launch(void* const* d_in, const int* in_sizes, int n_in,
                              void* d_out, int out_size)
{
    const float* x     = (const float*)d_in[0];
    const float* w_pre = (const float*)d_in[1];
    const float* b_pre = (const float*)d_in[2];
    const float* bn1g  = (const float*)d_in[3];
    const float* bn1b  = (const float*)d_in[4];
    const float* bn1m  = (const float*)d_in[5];
    const float* bn1v  = (const float*)d_in[6];
    const float* w_q   = (const float*)d_in[7];
    const float* b_q   = (const float*)d_in[8];
    const float* w_k   = (const float*)d_in[9];
    const float* b_k   = (const float*)d_in[10];
    const float* w_v   = (const float*)d_in[11];
    const float* b_v   = (const float*)d_in[12];
    const float* w_f   = (const float*)d_in[13];
    const float* b_f   = (const float*)d_in[14];
    const float* bn2g  = (const float*)d_in[15];
    const float* bn2b  = (const float*)d_in[16];
    const float* bn2m  = (const float*)d_in[17];
    const float* bn2v  = (const float*)d_in[18];
    const float* gamma = (const float*)d_in[19];
    float* out = (float*)d_out;

    float *x1, *q, *k, *v, *of, *attn;
    cudaGetSymbolAddress((void**)&x1,   g_x1);
    cudaGetSymbolAddress((void**)&q,    g_q);
    cudaGetSymbolAddress((void**)&k,    g_k);
    cudaGetSymbolAddress((void**)&v,    g_v);
    cudaGetSymbolAddress((void**)&of,   g_of);
    cudaGetSymbolAddress((void**)&attn, g_attn);

    const long long bX1 = (long long)CC * NPIX;
    const long long bQK = (long long)CR * NPIX;
    const long long bAT = (long long)NPIX * NPIX;

    // 1) conv1 + BN + ReLU -> x1  (3xTF32, prefetch-pipelined)
    conv3x3_tc<<<dim3(NPIX / 128, 2, BB), 256>>>(
        x, w_pre, b_pre, bn1g, bn1b, bn1m, bn1v, x1, CIN1);

    // 2) fused q+k projection (3xTF32, fp32-grade), v projection (1x tf32)
    qk_proj_3x<<<dim3(NPIX / 128, 1, BB), 256>>>(
        w_q, w_k, b_q, b_k, x1, bX1, q, k, bQK);
    gemm16_tf32<<<dim3(NPIX / 128, CC / 128, BB), 256>>>(
        w_v, 0, CC, x1, bX1, NPIX, 1, v, bX1, CC, NPIX, CC, b_v, nullptr, 0, nullptr);

    // 3-5) attention in chunks of CHUNK batches
    for (int c0 = 0; c0 < BB; c0 += CHUNK) {
        const float* qb = q  + (size_t)c0 * bQK;
        const float* kb = k  + (size_t)c0 * bQK;
        const float* vb = v  + (size_t)c0 * bX1;
        const float* xb = x1 + (size_t)c0 * bX1;
        float*       ob = of + (size_t)c0 * bX1;

        energy_3xtf32<<<dim3(NPIX / 128, NPIX / 128, CHUNK), 256>>>(
            qb, kb, attn, bQK, bAT);

        softmax_rows<<<CHUNK * NPIX, 256>>>(attn);

        // attn*V + residual: 1x tf32, prefetch-pipelined
        gemm16_tf32<<<dim3(NPIX / 128, CC / 128, CHUNK), 256>>>(
            vb, bX1, NPIX, attn, bAT, 1, NPIX,
            ob, bX1, CC, NPIX, NPIX, nullptr, xb, bX1, gamma);
    }

    // 6) conv2 + BN + ReLU -> d_out (3xTF32, prefetch-pipelined)
    conv3x3_tc<<<dim3(NPIX / 128, 2, BB), 256>>>(
        of, w_f, b_f, bn2g, bn2b, bn2m, bn2v, out, CC);
}